// round 2
// baseline (speedup 1.0000x reference)
#include <cuda_runtime.h>
#include <cuda_bf16.h>
#include <math.h>

// ---------------------------------------------------------------------------
// Problem constants
// ---------------------------------------------------------------------------
#define B_   16
#define N_   3136          // 56*56
#define DIM  512
#define HEADS 8
#define WS   7
#define HW   56
#define SD   256           // DIM/2
#define S_   32            // SD/HEADS
#define BN   (B_ * N_)     // 50176 rows
#define ELEMS ((long)BN * DIM)   // 25,690,112

// Scratch (static __device__ arrays; cudaMalloc is forbidden)
__device__ float g_buf1[ELEMS];   // dwconv out, then q
__device__ float g_buf2[ELEMS];   // kv (pwconv out)
__device__ float g_buf3[ELEMS];   // attention output (pre-proj)
__device__ float g_k[2 * B_ * HEADS * 49 * S_];   // pre-scaled by 1/sqrt(32)
__device__ float g_v[2 * B_ * HEADS * 49 * S_];

// ---------------------------------------------------------------------------
// 3x3 depthwise conv, pad 1, layout (B, N=H*W, C) channel-contiguous
// ---------------------------------------------------------------------------
__global__ void dwconv_kernel(const float* __restrict__ x,
                              const float* __restrict__ w,
                              const float* __restrict__ bias,
                              float* __restrict__ out) {
    int p = blockIdx.x;               // 0..BN-1
    int b = p / N_;
    int pix = p - b * N_;
    int hy = pix / HW, hx = pix - hy * HW;
    int c = threadIdx.x;              // 512 threads
    float acc = bias[c];
    #pragma unroll
    for (int dy = 0; dy < 3; dy++) {
        int yy = hy + dy - 1;
        if (yy < 0 || yy >= HW) continue;
        #pragma unroll
        for (int dx = 0; dx < 3; dx++) {
            int xx = hx + dx - 1;
            if (xx < 0 || xx >= HW) continue;
            acc += w[c * 9 + dy * 3 + dx] *
                   x[((long)b * N_ + yy * HW + xx) * DIM + c];
        }
    }
    out[(long)p * DIM + c] = acc;
}

// ---------------------------------------------------------------------------
// SGEMM: C[M,512] = A[M,512] @ W[512,512]^T (+ bias)
// 64x64 tile, 256 threads, 4x4 microtile, K-tile 16
// ---------------------------------------------------------------------------
__global__ void gemm64_kernel(const float* __restrict__ A,
                              const float* __restrict__ W,
                              const float* __restrict__ bias,
                              float* __restrict__ C) {
    const int K = DIM, N = DIM;
    __shared__ float As[16][68];
    __shared__ float Bs[16][68];
    int tid = threadIdx.x;
    int tx = tid & 15, ty = tid >> 4;
    long m0 = (long)blockIdx.x * 64;
    int n0 = blockIdx.y * 64;
    int lrow = tid >> 2;            // 0..63
    int lseg = (tid & 3) << 2;      // 0,4,8,12
    float acc[4][4] = {};

    const float* Ap = A + (m0 + lrow) * K + lseg;
    const float* Wp = W + (long)(n0 + lrow) * K + lseg;

    for (int k0 = 0; k0 < K; k0 += 16) {
        float4 av = *(const float4*)(Ap + k0);
        float4 bv = *(const float4*)(Wp + k0);
        As[lseg + 0][lrow] = av.x; As[lseg + 1][lrow] = av.y;
        As[lseg + 2][lrow] = av.z; As[lseg + 3][lrow] = av.w;
        Bs[lseg + 0][lrow] = bv.x; Bs[lseg + 1][lrow] = bv.y;
        Bs[lseg + 2][lrow] = bv.z; Bs[lseg + 3][lrow] = bv.w;
        __syncthreads();
        #pragma unroll
        for (int kk = 0; kk < 16; kk++) {
            float4 a = *(const float4*)&As[kk][ty << 2];
            float4 bq = *(const float4*)&Bs[kk][tx << 2];
            acc[0][0] += a.x * bq.x; acc[0][1] += a.x * bq.y;
            acc[0][2] += a.x * bq.z; acc[0][3] += a.x * bq.w;
            acc[1][0] += a.y * bq.x; acc[1][1] += a.y * bq.y;
            acc[1][2] += a.y * bq.z; acc[1][3] += a.y * bq.w;
            acc[2][0] += a.z * bq.x; acc[2][1] += a.z * bq.y;
            acc[2][2] += a.z * bq.z; acc[2][3] += a.z * bq.w;
            acc[3][0] += a.w * bq.x; acc[3][1] += a.w * bq.y;
            acc[3][2] += a.w * bq.z; acc[3][3] += a.w * bq.w;
        }
        __syncthreads();
    }
    #pragma unroll
    for (int ii = 0; ii < 4; ii++) {
        long mm = m0 + (ty << 2) + ii;
        #pragma unroll
        for (int jj = 0; jj < 4; jj++) {
            int nn = n0 + (tx << 2) + jj;
            float v = acc[ii][jj];
            if (bias) v += bias[nn];
            C[mm * N + nn] = v;
        }
    }
}

// ---------------------------------------------------------------------------
// Per (branch, b, head): unfold -> pooled -> fc -> single -> k/v, v += local dwconv
// ---------------------------------------------------------------------------
__global__ void prep_kernel(const float* __restrict__ kv,
                            const float* __restrict__ fc0, const float* __restrict__ fc1,
                            const float* __restrict__ sg0, const float* __restrict__ sg1,
                            const float* __restrict__ lw0, const float* __restrict__ lb0,
                            const float* __restrict__ lw1, const float* __restrict__ lb1) {
    int blk = blockIdx.x;       // 0..255 : (branch, b, h)
    int br = blk >> 7;
    int bh = blk & 127;
    int b = bh >> 3, h = bh & 7;
    int tid = threadIdx.x;      // 256

    __shared__ float pooled[49][32];
    __shared__ float tmp[49][32];
    __shared__ float vsh[49][33];

    int chbase = br * SD + h * S_;

    // pooled[w][s]
    for (int idx = tid; idx < 49 * 32; idx += 256) {
        int w = idx >> 5, s = idx & 31;
        int ky = w / 7, kx = w - ky * 7;
        float sum = 0.f;
        if (br == 0) {
            // LL=64, stride 7, dil 1: mean over windows {2s,2s+1}, all 32 ch
            #pragma unroll
            for (int t = 0; t < 2; t++) {
                int ll = 2 * s + t;
                int ly = ll >> 3, lx = ll & 7;
                int py = ly * 7 + ky, px = lx * 7 + kx;
                const float* src = kv + ((long)b * N_ + py * HW + px) * DIM + chbase;
                #pragma unroll
                for (int c = 0; c < 32; c++) sum += src[c];
            }
            sum *= (1.f / 64.f);
        } else {
            // LL=16, stride 13, dil 2: window s/2, channels 16*(s&1)..+16
            int ll = s >> 1;
            int ly = ll >> 2, lx = ll & 3;
            int py = ly * 13 + ky * 2, px = lx * 13 + kx * 2;
            const float* src = kv + ((long)b * N_ + py * HW + px) * DIM
                               + chbase + 16 * (s & 1);
            #pragma unroll
            for (int c = 0; c < 16; c++) sum += src[c];
            sum *= (1.f / 16.f);
        }
        pooled[w][s] = sum;
    }
    __syncthreads();

    // tmp = pooled @ fc^T
    const float* fc = br ? fc1 : fc0;
    for (int idx = tid; idx < 49 * 32; idx += 256) {
        int w = idx >> 5, t = idx & 31;
        float sum = 0.f;
        #pragma unroll
        for (int s = 0; s < 32; s++) sum += pooled[w][s] * fc[t * 32 + s];
        tmp[w][t] = sum;
    }
    __syncthreads();

    // kvp = tmp @ single^T ; j<32 -> k (scaled), j>=32 -> v
    const float* sg = br ? sg1 : sg0;
    const float kscale = 0.17677669529663689f;  // 1/sqrt(32)
    for (int idx = tid; idx < 49 * 64; idx += 256) {
        int w = idx >> 6, j = idx & 63;
        float sum = 0.f;
        #pragma unroll
        for (int t = 0; t < 32; t++) sum += tmp[w][t] * sg[j * 32 + t];
        if (j < 32)
            g_k[(long)blk * 49 * 32 + w * 32 + j] = sum * kscale;
        else
            vsh[w][j - 32] = sum;
    }
    __syncthreads();

    // v += 3x3 depthwise conv over the 7x7 window grid (+bias)
    const float* lw = br ? lw1 : lw0;
    const float* lb = br ? lb1 : lb0;
    for (int idx = tid; idx < 49 * 32; idx += 256) {
        int w = idx >> 5, s = idx & 31;
        int wy = w / 7, wx = w - wy * 7;
        int ch = h * S_ + s;
        float acc = vsh[w][s] + lb[ch];
        #pragma unroll
        for (int dy = 0; dy < 3; dy++) {
            int yy = wy + dy - 1;
            if (yy < 0 || yy >= 7) continue;
            #pragma unroll
            for (int dx = 0; dx < 3; dx++) {
                int xx = wx + dx - 1;
                if (xx < 0 || xx >= 7) continue;
                acc += lw[ch * 9 + dy * 3 + dx] * vsh[yy * 7 + xx][s];
            }
        }
        g_v[(long)blk * 49 * 32 + w * 32 + s] = acc;
    }
}

// ---------------------------------------------------------------------------
// Attention: per (branch,b,h) block-column, thread-per-query, 49 keys in smem
// ---------------------------------------------------------------------------
__global__ void attn_kernel(const float* __restrict__ q,
                            float* __restrict__ att) {
    int blk = blockIdx.x;       // (branch, b, h)
    int br = blk >> 7;
    int bh = blk & 127;
    int b = bh >> 3, h = bh & 7;
    int tid = threadIdx.x;      // 256

    __shared__ float ksh[49][32];
    __shared__ float vsh[49][32];
    __shared__ float osh[256][33];

    const float* kp = g_k + (long)blk * 1568;
    const float* vp = g_v + (long)blk * 1568;
    for (int idx = tid; idx < 1568; idx += 256) {
        ((float*)ksh)[idx] = kp[idx];
        ((float*)vsh)[idx] = vp[idx];
    }
    __syncthreads();

    int n0 = blockIdx.y * 256;
    int n = n0 + tid;
    float p[49];
    if (n < N_) {
        const float* qp = q + ((long)b * N_ + n) * DIM + h * 64 + br * 32;
        float4 qv4[8];
        #pragma unroll
        for (int v = 0; v < 8; v++) qv4[v] = *(const float4*)(qp + v * 4);
        float qv[32];
        #pragma unroll
        for (int v = 0; v < 8; v++) {
            qv[v * 4 + 0] = qv4[v].x; qv[v * 4 + 1] = qv4[v].y;
            qv[v * 4 + 2] = qv4[v].z; qv[v * 4 + 3] = qv4[v].w;
        }
        float m = -1e30f;
        #pragma unroll
        for (int j = 0; j < 49; j++) {
            float s = 0.f;
            #pragma unroll
            for (int d = 0; d < 32; d++) s += qv[d] * ksh[j][d];
            p[j] = s;
            m = fmaxf(m, s);
        }
        float sum = 0.f;
        #pragma unroll
        for (int j = 0; j < 49; j++) { p[j] = __expf(p[j] - m); sum += p[j]; }
        float inv = 1.f / sum;
        #pragma unroll
        for (int d = 0; d < 32; d++) {
            float acc = 0.f;
            #pragma unroll
            for (int j = 0; j < 49; j++) acc += p[j] * vsh[j][d];
            osh[tid][d] = acc * inv;
        }
    }
    __syncthreads();

    // coalesced write: channel = br*256 + h*32 + d
    int off = br * SD + h * S_;
    for (int idx = tid; idx < 256 * 32; idx += 256) {
        int qq = idx >> 5, d = idx & 31;
        int nn = n0 + qq;
        if (nn < N_) att[((long)b * N_ + nn) * DIM + off + d] = osh[qq][d];
    }
}

// ---------------------------------------------------------------------------
// Launch
// ---------------------------------------------------------------------------
extern "C" void kernel_launch(void* const* d_in, const int* in_sizes, int n_in,
                              void* d_out, int out_size) {
    const float* x        = (const float*)d_in[0];
    // d_in[1], d_in[2] are H, W scalars (56) — hardcoded
    const float* q_w      = (const float*)d_in[3];
    const float* kv_dw_w  = (const float*)d_in[4];
    const float* kv_dw_b  = (const float*)d_in[5];
    const float* kv_pw_w  = (const float*)d_in[6];
    const float* kv_pw_b  = (const float*)d_in[7];
    const float* fc_w0    = (const float*)d_in[8];
    const float* fc_w1    = (const float*)d_in[9];
    const float* sg_w0    = (const float*)d_in[10];
    const float* sg_w1    = (const float*)d_in[11];
    const float* lw0      = (const float*)d_in[12];
    const float* lb0      = (const float*)d_in[13];
    const float* lw1      = (const float*)d_in[14];
    const float* lb1      = (const float*)d_in[15];
    const float* proj_w   = (const float*)d_in[16];
    const float* proj_b   = (const float*)d_in[17];
    float* out = (float*)d_out;

    float *buf1, *buf2, *buf3;
    cudaGetSymbolAddress((void**)&buf1, g_buf1);
    cudaGetSymbolAddress((void**)&buf2, g_buf2);
    cudaGetSymbolAddress((void**)&buf3, g_buf3);

    dim3 ggrid(BN / 64, DIM / 64);   // 784 x 8

    // 1) depthwise conv on x -> buf1
    dwconv_kernel<<<BN, DIM>>>(x, kv_dw_w, kv_dw_b, buf1);
    // 2) pointwise conv: kv = buf1 @ pw^T + b -> buf2
    gemm64_kernel<<<ggrid, 256>>>(buf1, kv_pw_w, kv_pw_b, buf2);
    // 3) q = x @ q_w^T -> buf1 (dw output no longer needed)
    gemm64_kernel<<<ggrid, 256>>>(x, q_w, nullptr, buf1);
    // 4) branch prep (pool/fc/single/local dwconv) -> g_k, g_v
    prep_kernel<<<256, 256>>>(buf2, fc_w0, fc_w1, sg_w0, sg_w1,
                              lw0, lb0, lw1, lb1);
    // 5) attention -> buf3
    attn_kernel<<<dim3(256, (N_ + 255) / 256), 256>>>(buf1, buf3);
    // 6) out = buf3 @ proj^T + bias
    gemm64_kernel<<<ggrid, 256>>>(buf3, proj_w, proj_b, out);
}

// round 4
// speedup vs baseline: 2.1685x; 2.1685x over previous
#include <cuda_runtime.h>
#include <cuda_bf16.h>
#include <cstdint>

#define B_    16
#define N_    3136
#define DIM   512
#define HEADS 8
#define HW    56
#define SD    256
#define S_    32
#define BN    (B_ * N_)
#define ELEMS ((long)BN * DIM)

// ---------------- scratch ----------------
__device__ __nv_bfloat16 g_xhi[ELEMS], g_xlo[ELEMS];
__device__ __nv_bfloat16 g_d1hi[ELEMS], g_d1lo[ELEMS];
__device__ __nv_bfloat16 g_a3hi[ELEMS], g_a3lo[ELEMS];
__device__ __nv_bfloat16 g_wh[3][DIM * DIM], g_wl[3][DIM * DIM];
__device__ float g_q[ELEMS];
__device__ float g_kv[ELEMS];
__device__ float g_k[2 * B_ * HEADS * 49 * S_];
__device__ float g_v[2 * B_ * HEADS * 49 * S_];

// ---------------- helpers ----------------
__device__ __forceinline__ uint32_t smem_u32(const void* p) {
    uint32_t a;
    asm("{ .reg .u64 t; cvta.to.shared.u64 t, %1; cvt.u32.u64 %0, t; }" : "=r"(a) : "l"(p));
    return a;
}
__device__ __forceinline__ void cp16(uint32_t d, const void* g) {
    asm volatile("cp.async.cg.shared.global [%0], [%1], 16;" :: "r"(d), "l"(g));
}
#define CP_COMMIT() asm volatile("cp.async.commit_group;" ::: "memory")
#define CP_WAIT(n)  asm volatile("cp.async.wait_group %0;" :: "n"(n) : "memory")

#define LDSM_X4(r, a) \
    asm volatile("ldmatrix.sync.aligned.m8n8.x4.shared.b16 {%0,%1,%2,%3}, [%4];" \
        : "=r"((r)[0]), "=r"((r)[1]), "=r"((r)[2]), "=r"((r)[3]) : "r"(a))
#define LDSM_X2(r, a) \
    asm volatile("ldmatrix.sync.aligned.m8n8.x2.shared.b16 {%0,%1}, [%2];" \
        : "=r"((r)[0]), "=r"((r)[1]) : "r"(a))
#define MMA16816(c, a, b) \
    asm volatile("mma.sync.aligned.m16n8k16.row.col.f32.bf16.bf16.f32 " \
        "{%0,%1,%2,%3},{%4,%5,%6,%7},{%8,%9},{%0,%1,%2,%3};" \
        : "+f"((c)[0]), "+f"((c)[1]), "+f"((c)[2]), "+f"((c)[3]) \
        : "r"((a)[0]), "r"((a)[1]), "r"((a)[2]), "r"((a)[3]), "r"((b)[0]), "r"((b)[1]))

__device__ __forceinline__ void split2(float v, __nv_bfloat16& h, __nv_bfloat16& l) {
    h = __float2bfloat16(v);
    l = __float2bfloat16(v - __bfloat162float(h));
}

// ---------------- split fp32 -> hi/lo bf16 ----------------
__global__ void split_kernel(const float* __restrict__ src, __nv_bfloat16* __restrict__ hi,
                             __nv_bfloat16* __restrict__ lo, long n4) {
    long i = (long)blockIdx.x * blockDim.x + threadIdx.x;
    if (i >= n4) return;
    float4 v = ((const float4*)src)[i];
    __nv_bfloat16 h0,h1,h2,h3,l0,l1,l2,l3;
    split2(v.x,h0,l0); split2(v.y,h1,l1); split2(v.z,h2,l2); split2(v.w,h3,l3);
    ((__nv_bfloat162*)hi)[i*2]   = {h0,h1}; ((__nv_bfloat162*)hi)[i*2+1] = {h2,h3};
    ((__nv_bfloat162*)lo)[i*2]   = {l0,l1}; ((__nv_bfloat162*)lo)[i*2+1] = {l2,l3};
}

// ---------------- 3x3 depthwise conv, write splits ----------------
__global__ void dwconv_kernel(const float* __restrict__ x, const float* __restrict__ w,
                              const float* __restrict__ bias,
                              __nv_bfloat16* __restrict__ ohi, __nv_bfloat16* __restrict__ olo) {
    int p = blockIdx.x;
    int b = p / N_, pix = p - b * N_;
    int hy = pix / HW, hx = pix - hy * HW;
    int c = threadIdx.x;
    float acc = bias[c];
    #pragma unroll
    for (int dy = 0; dy < 3; dy++) {
        int yy = hy + dy - 1;
        if (yy < 0 || yy >= HW) continue;
        #pragma unroll
        for (int dx = 0; dx < 3; dx++) {
            int xx = hx + dx - 1;
            if (xx < 0 || xx >= HW) continue;
            acc += w[c*9 + dy*3 + dx] * x[((long)b*N_ + yy*HW + xx)*DIM + c];
        }
    }
    __nv_bfloat16 h, l; split2(acc, h, l);
    ohi[(long)p*DIM + c] = h; olo[(long)p*DIM + c] = l;
}

// ---------------------------------------------------------------------------
// mma.sync bf16x3 GEMM: C[M,512] = A @ W^T (+bias), fp32 out
// block 128x128, 8 warps (2Mx4N), warp tile 64x32, K-chunk 32, 2-stage cp.async
// Shared per stage: Ah|Al|Wh|Wl, each 128 rows x 40 bf16 (80B stride, pad)
// ---------------------------------------------------------------------------
#define STAGE_B  40960
#define GSMEM    (2 * STAGE_B)

__global__ void __launch_bounds__(256)
gemm_mma(const __nv_bfloat16* __restrict__ Ah, const __nv_bfloat16* __restrict__ Al,
         const __nv_bfloat16* __restrict__ Wh, const __nv_bfloat16* __restrict__ Wl,
         const float* __restrict__ bias, float* __restrict__ C) {
    extern __shared__ char smem[];
    uint32_t sb = smem_u32(smem);
    const int tid = threadIdx.x, lane = tid & 31, wid = tid >> 5;
    const int wm = wid & 1, wn = wid >> 1;
    const long m0 = (long)blockIdx.x * 128;
    const int n0 = blockIdx.y * 128;

    auto load_chunk = [&](int ck, int st) {
        uint32_t base = sb + st * STAGE_B;
        #pragma unroll
        for (int it = 0; it < 8; it++) {
            int idx = tid + it * 256;        // 0..2047
            int arr = idx >> 9;              // 0:Ah 1:Al 2:Wh 3:Wl
            int loc = idx & 511;
            int r = loc >> 2, seg = loc & 3;
            const __nv_bfloat16* g;
            if (arr == 0)      g = Ah + (m0 + r) * DIM + ck * 32 + seg * 8;
            else if (arr == 1) g = Al + (m0 + r) * DIM + ck * 32 + seg * 8;
            else if (arr == 2) g = Wh + (long)(n0 + r) * DIM + ck * 32 + seg * 8;
            else               g = Wl + (long)(n0 + r) * DIM + ck * 32 + seg * 8;
            cp16(base + arr * 10240 + r * 80 + seg * 16, g);
        }
        CP_COMMIT();
    };

    float acc[4][4][4];
    #pragma unroll
    for (int i = 0; i < 4; i++)
        #pragma unroll
        for (int j = 0; j < 4; j++)
            #pragma unroll
            for (int r = 0; r < 4; r++) acc[i][j][r] = 0.f;

    load_chunk(0, 0);

    // ldmatrix lane address components
    const int arow = lane & 15;                  // A: rows 0..15
    const int acolB = (lane >> 4) ? 16 : 0;      // +16B for k cols 8..15
    const int brow = lane & 7;                   // B: 8 n-rows
    const int bcolB = ((lane >> 3) & 1) ? 16 : 0;

    for (int c = 0; c < 16; c++) {
        if (c + 1 < 16) { load_chunk(c + 1, (c + 1) & 1); CP_WAIT(1); }
        else            { CP_WAIT(0); }
        __syncthreads();
        uint32_t base = sb + (c & 1) * STAGE_B;
        #pragma unroll
        for (int ks = 0; ks < 2; ks++) {
            const int kb = ks * 32;              // 16 bf16 = 32B
            uint32_t ah[4][4], al[4][4];
            #pragma unroll
            for (int i = 0; i < 4; i++) {
                uint32_t addr = base + (wm * 64 + i * 16 + arow) * 80 + kb + acolB;
                LDSM_X4(ah[i], addr);
                LDSM_X4(al[i], addr + 10240);
            }
            #pragma unroll
            for (int j = 0; j < 4; j++) {
                uint32_t baddr = base + 20480 + (wn * 32 + j * 8 + brow) * 80 + kb + bcolB;
                uint32_t wh2[2], wl2[2];
                LDSM_X2(wh2, baddr);
                LDSM_X2(wl2, baddr + 10240);
                #pragma unroll
                for (int i = 0; i < 4; i++) {
                    MMA16816(acc[i][j], ah[i], wh2);
                    MMA16816(acc[i][j], al[i], wh2);
                    MMA16816(acc[i][j], ah[i], wl2);
                }
            }
        }
        __syncthreads();
    }

    // epilogue
    #pragma unroll
    for (int i = 0; i < 4; i++) {
        long r0 = m0 + wm * 64 + i * 16 + (lane >> 2);
        #pragma unroll
        for (int j = 0; j < 4; j++) {
            int col = n0 + wn * 32 + j * 8 + (lane & 3) * 2;
            float b0 = 0.f, b1 = 0.f;
            if (bias) { b0 = bias[col]; b1 = bias[col + 1]; }
            float2 v0 = { acc[i][j][0] + b0, acc[i][j][1] + b1 };
            float2 v1 = { acc[i][j][2] + b0, acc[i][j][3] + b1 };
            *(float2*)(C + r0 * DIM + col) = v0;
            *(float2*)(C + (r0 + 8) * DIM + col) = v1;
        }
    }
}

// ---------------- prep: unfold/pool/fc/single/local per (branch,b,h) ----------------
__global__ void prep_kernel(const float* __restrict__ kv,
                            const float* __restrict__ fc0, const float* __restrict__ fc1,
                            const float* __restrict__ sg0, const float* __restrict__ sg1,
                            const float* __restrict__ lw0, const float* __restrict__ lb0,
                            const float* __restrict__ lw1, const float* __restrict__ lb1) {
    int blk = blockIdx.x;
    int br = blk >> 7, bh = blk & 127, b = bh >> 3, h = bh & 7;
    int tid = threadIdx.x;
    __shared__ float pooled[49][32], tmp[49][32], vsh[49][33];
    int chbase = br * SD + h * S_;

    for (int idx = tid; idx < 49*32; idx += 256) {
        int w = idx >> 5, s = idx & 31;
        int ky = w / 7, kx = w - ky * 7;
        float sum = 0.f;
        if (br == 0) {
            #pragma unroll
            for (int t = 0; t < 2; t++) {
                int ll = 2*s + t, ly = ll >> 3, lx = ll & 7;
                const float* src = kv + ((long)b*N_ + (ly*7+ky)*HW + lx*7+kx)*DIM + chbase;
                #pragma unroll
                for (int cc = 0; cc < 32; cc++) sum += src[cc];
            }
            sum *= (1.f/64.f);
        } else {
            int ll = s >> 1, ly = ll >> 2, lx = ll & 3;
            const float* src = kv + ((long)b*N_ + (ly*13+ky*2)*HW + lx*13+kx*2)*DIM + chbase + 16*(s&1);
            #pragma unroll
            for (int cc = 0; cc < 16; cc++) sum += src[cc];
            sum *= (1.f/16.f);
        }
        pooled[w][s] = sum;
    }
    __syncthreads();
    const float* fc = br ? fc1 : fc0;
    for (int idx = tid; idx < 49*32; idx += 256) {
        int w = idx >> 5, t = idx & 31;
        float sum = 0.f;
        #pragma unroll
        for (int s = 0; s < 32; s++) sum += pooled[w][s] * fc[t*32+s];
        tmp[w][t] = sum;
    }
    __syncthreads();
    const float* sg = br ? sg1 : sg0;
    const float kscale = 0.17677669529663689f;
    for (int idx = tid; idx < 49*64; idx += 256) {
        int w = idx >> 6, j = idx & 63;
        float sum = 0.f;
        #pragma unroll
        for (int t = 0; t < 32; t++) sum += tmp[w][t] * sg[j*32+t];
        if (j < 32) g_k[(long)blk*1568 + w*32 + j] = sum * kscale;
        else        vsh[w][j-32] = sum;
    }
    __syncthreads();
    const float* lw = br ? lw1 : lw0;
    const float* lb = br ? lb1 : lb0;
    for (int idx = tid; idx < 49*32; idx += 256) {
        int w = idx >> 5, s = idx & 31;
        int wy = w / 7, wx = w - wy * 7, ch = h*S_ + s;
        float acc = vsh[w][s] + lb[ch];
        #pragma unroll
        for (int dy = 0; dy < 3; dy++) {
            int yy = wy + dy - 1;
            if (yy < 0 || yy >= 7) continue;
            #pragma unroll
            for (int dx = 0; dx < 3; dx++) {
                int xx = wx + dx - 1;
                if (xx < 0 || xx >= 7) continue;
                acc += lw[ch*9 + dy*3 + dx] * vsh[yy*7+xx][s];
            }
        }
        g_v[(long)blk*1568 + w*32 + s] = acc;
    }
}

// ---------------- attention: thread-per-query, write bf16 splits ----------------
__global__ void attn_kernel(const float* __restrict__ q,
                            __nv_bfloat16* __restrict__ ahi, __nv_bfloat16* __restrict__ alo) {
    int blk = blockIdx.x;
    int br = blk >> 7, bh = blk & 127, b = bh >> 3, h = bh & 7;
    int tid = threadIdx.x;
    __shared__ float ksh[49][32], vsh[49][32], osh[256][33];
    const float* kp = g_k + (long)blk * 1568;
    const float* vp = g_v + (long)blk * 1568;
    for (int idx = tid; idx < 1568; idx += 256) { ((float*)ksh)[idx] = kp[idx]; ((float*)vsh)[idx] = vp[idx]; }
    __syncthreads();

    int n0 = blockIdx.y * 256, n = n0 + tid;
    if (n < N_) {
        const float* qp = q + ((long)b*N_ + n)*DIM + h*64 + br*32;
        float qv[32];
        #pragma unroll
        for (int v = 0; v < 8; v++) {
            float4 t = *(const float4*)(qp + v*4);
            qv[v*4]=t.x; qv[v*4+1]=t.y; qv[v*4+2]=t.z; qv[v*4+3]=t.w;
        }
        float p[49], m = -1e30f;
        #pragma unroll
        for (int j = 0; j < 49; j++) {
            float s = 0.f;
            #pragma unroll
            for (int d = 0; d < 32; d++) s += qv[d] * ksh[j][d];
            p[j] = s; m = fmaxf(m, s);
        }
        float sum = 0.f;
        #pragma unroll
        for (int j = 0; j < 49; j++) { p[j] = __expf(p[j] - m); sum += p[j]; }
        float inv = 1.f / sum;
        #pragma unroll
        for (int d = 0; d < 32; d++) {
            float acc = 0.f;
            #pragma unroll
            for (int j = 0; j < 49; j++) acc += p[j] * vsh[j][d];
            osh[tid][d] = acc * inv;
        }
    }
    __syncthreads();
    int off = br * SD + h * S_;
    for (int idx = tid; idx < 256*16; idx += 256) {
        int qq = idx >> 4, dp = (idx & 15) * 2;
        int nn = n0 + qq;
        if (nn < N_) {
            __nv_bfloat16 h0,l0,h1,l1;
            split2(osh[qq][dp], h0, l0); split2(osh[qq][dp+1], h1, l1);
            long o = ((long)b*N_ + nn)*DIM + off + dp;
            *(__nv_bfloat162*)(ahi + o) = {h0, h1};
            *(__nv_bfloat162*)(alo + o) = {l0, l1};
        }
    }
}

// ---------------- launch ----------------
extern "C" void kernel_launch(void* const* d_in, const int* in_sizes, int n_in,
                              void* d_out, int out_size) {
    const float* x       = (const float*)d_in[0];
    const float* q_w     = (const float*)d_in[3];
    const float* kv_dw_w = (const float*)d_in[4];
    const float* kv_dw_b = (const float*)d_in[5];
    const float* kv_pw_w = (const float*)d_in[6];
    const float* kv_pw_b = (const float*)d_in[7];
    const float* fc_w0   = (const float*)d_in[8];
    const float* fc_w1   = (const float*)d_in[9];
    const float* sg_w0   = (const float*)d_in[10];
    const float* sg_w1   = (const float*)d_in[11];
    const float* lw0     = (const float*)d_in[12];
    const float* lb0     = (const float*)d_in[13];
    const float* lw1     = (const float*)d_in[14];
    const float* lb1     = (const float*)d_in[15];
    const float* proj_w  = (const float*)d_in[16];
    const float* proj_b  = (const float*)d_in[17];
    float* out = (float*)d_out;

    __nv_bfloat16 *xhi, *xlo, *d1hi, *d1lo, *a3hi, *a3lo, *wh, *wl;
    float *qb, *kvb;
    cudaGetSymbolAddress((void**)&xhi, g_xhi);   cudaGetSymbolAddress((void**)&xlo, g_xlo);
    cudaGetSymbolAddress((void**)&d1hi, g_d1hi); cudaGetSymbolAddress((void**)&d1lo, g_d1lo);
    cudaGetSymbolAddress((void**)&a3hi, g_a3hi); cudaGetSymbolAddress((void**)&a3lo, g_a3lo);
    cudaGetSymbolAddress((void**)&wh, g_wh);     cudaGetSymbolAddress((void**)&wl, g_wl);
    cudaGetSymbolAddress((void**)&qb, g_q);      cudaGetSymbolAddress((void**)&kvb, g_kv);

    cudaFuncSetAttribute(gemm_mma, cudaFuncAttributeMaxDynamicSharedMemorySize, GSMEM);

    const long WN4 = DIM * DIM / 4;
    split_kernel<<<(WN4 + 255) / 256, 256>>>(q_w,     wh,             wl,             WN4);
    split_kernel<<<(WN4 + 255) / 256, 256>>>(kv_pw_w, wh + DIM*DIM,   wl + DIM*DIM,   WN4);
    split_kernel<<<(WN4 + 255) / 256, 256>>>(proj_w,  wh + 2*DIM*DIM, wl + 2*DIM*DIM, WN4);
    split_kernel<<<(ELEMS/4 + 255) / 256, 256>>>(x, xhi, xlo, ELEMS / 4);
    dwconv_kernel<<<BN, DIM>>>(x, kv_dw_w, kv_dw_b, d1hi, d1lo);

    dim3 gg(BN / 128, DIM / 128);    // 392 x 4
    gemm_mma<<<gg, 256, GSMEM>>>(d1hi, d1lo, wh + DIM*DIM, wl + DIM*DIM, kv_pw_b, kvb);
    gemm_mma<<<gg, 256, GSMEM>>>(xhi,  xlo,  wh,           wl,           nullptr, qb);
    prep_kernel<<<256, 256>>>(kvb, fc_w0, fc_w1, sg_w0, sg_w1, lw0, lb0, lw1, lb1);
    attn_kernel<<<dim3(256, (N_ + 255) / 256), 256>>>(qb, a3hi, a3lo);
    gemm_mma<<<gg, 256, GSMEM>>>(a3hi, a3lo, wh + 2*DIM*DIM, wl + 2*DIM*DIM, proj_b, out);
}

// round 5
// speedup vs baseline: 2.6640x; 1.2285x over previous
#include <cuda_runtime.h>
#include <cuda_bf16.h>
#include <cstdint>

#define B_    16
#define N_    3136
#define DIM   512
#define HEADS 8
#define HW    56
#define SD    256
#define S_    32
#define BN    (B_ * N_)
#define ELEMS ((long)BN * DIM)

// ---------------- scratch ----------------
__device__ __nv_bfloat16 g_xhi[ELEMS], g_xlo[ELEMS];
__device__ __nv_bfloat16 g_d1hi[ELEMS], g_d1lo[ELEMS];
__device__ __nv_bfloat16 g_a3hi[ELEMS], g_a3lo[ELEMS];
__device__ __nv_bfloat16 g_wh[3][DIM * DIM], g_wl[3][DIM * DIM];
__device__ float g_q[ELEMS];
__device__ float g_kv[ELEMS];
__device__ float g_half[B_][32][N_];          // 16-ch half sums of kv
__device__ float g_k[2 * B_ * HEADS * 49 * S_];
__device__ float g_v[2 * B_ * HEADS * 49 * S_];

// ---------------- helpers ----------------
__device__ __forceinline__ uint32_t smem_u32(const void* p) {
    uint32_t a;
    asm("{ .reg .u64 t; cvta.to.shared.u64 t, %1; cvt.u32.u64 %0, t; }" : "=r"(a) : "l"(p));
    return a;
}
__device__ __forceinline__ void cp16(uint32_t d, const void* g) {
    asm volatile("cp.async.cg.shared.global [%0], [%1], 16;" :: "r"(d), "l"(g));
}
#define CP_COMMIT() asm volatile("cp.async.commit_group;" ::: "memory")
#define CP_WAIT(n)  asm volatile("cp.async.wait_group %0;" :: "n"(n) : "memory")

#define LDSM_X4(r, a) \
    asm volatile("ldmatrix.sync.aligned.m8n8.x4.shared.b16 {%0,%1,%2,%3}, [%4];" \
        : "=r"((r)[0]), "=r"((r)[1]), "=r"((r)[2]), "=r"((r)[3]) : "r"(a))
#define LDSM_X2(r, a) \
    asm volatile("ldmatrix.sync.aligned.m8n8.x2.shared.b16 {%0,%1}, [%2];" \
        : "=r"((r)[0]), "=r"((r)[1]) : "r"(a))
#define MMA16816(c, a, b) \
    asm volatile("mma.sync.aligned.m16n8k16.row.col.f32.bf16.bf16.f32 " \
        "{%0,%1,%2,%3},{%4,%5,%6,%7},{%8,%9},{%0,%1,%2,%3};" \
        : "+f"((c)[0]), "+f"((c)[1]), "+f"((c)[2]), "+f"((c)[3]) \
        : "r"((a)[0]), "r"((a)[1]), "r"((a)[2]), "r"((a)[3]), "r"((b)[0]), "r"((b)[1]))

__device__ __forceinline__ void split2(float v, __nv_bfloat16& h, __nv_bfloat16& l) {
    h = __float2bfloat16(v);
    l = __float2bfloat16(v - __bfloat162float(h));
}

// ---------------- split fp32 -> hi/lo bf16 (weights only) ----------------
__global__ void split_kernel(const float* __restrict__ src, __nv_bfloat16* __restrict__ hi,
                             __nv_bfloat16* __restrict__ lo, long n4) {
    long i = (long)blockIdx.x * blockDim.x + threadIdx.x;
    if (i >= n4) return;
    float4 v = ((const float4*)src)[i];
    __nv_bfloat16 h0,h1,h2,h3,l0,l1,l2,l3;
    split2(v.x,h0,l0); split2(v.y,h1,l1); split2(v.z,h2,l2); split2(v.w,h3,l3);
    ((__nv_bfloat162*)hi)[i*2]   = {h0,h1}; ((__nv_bfloat162*)hi)[i*2+1] = {h2,h3};
    ((__nv_bfloat162*)lo)[i*2]   = {l0,l1}; ((__nv_bfloat162*)lo)[i*2+1] = {l2,l3};
}

// ---------------- 3x3 depthwise conv + fused x split ----------------
__global__ void dwconv_kernel(const float* __restrict__ x, const float* __restrict__ w,
                              const float* __restrict__ bias,
                              __nv_bfloat16* __restrict__ ohi, __nv_bfloat16* __restrict__ olo,
                              __nv_bfloat16* __restrict__ xhi, __nv_bfloat16* __restrict__ xlo) {
    int p = blockIdx.x;
    int b = p / N_, pix = p - b * N_;
    int hy = pix / HW, hx = pix - hy * HW;
    int c = threadIdx.x;
    float acc = bias[c];
    float xc = 0.f;
    #pragma unroll
    for (int dy = 0; dy < 3; dy++) {
        int yy = hy + dy - 1;
        if (yy < 0 || yy >= HW) continue;
        #pragma unroll
        for (int dx = 0; dx < 3; dx++) {
            int xx = hx + dx - 1;
            if (xx < 0 || xx >= HW) continue;
            float v = x[((long)b*N_ + yy*HW + xx)*DIM + c];
            if (dy == 1 && dx == 1) xc = v;
            acc += w[c*9 + dy*3 + dx] * v;
        }
    }
    __nv_bfloat16 h, l;
    split2(acc, h, l);
    ohi[(long)p*DIM + c] = h; olo[(long)p*DIM + c] = l;
    split2(xc, h, l);
    xhi[(long)p*DIM + c] = h; xlo[(long)p*DIM + c] = l;
}

// ---------------------------------------------------------------------------
// mma.sync bf16x3 GEMM: C[M,512] = A @ W^T (+bias)
// block 128x128, 8 warps, warp tile 64x32, K-chunk 32, 2-stage cp.async
// ---------------------------------------------------------------------------
#define STAGE_B  40960
#define GSMEM    (2 * STAGE_B)

__global__ void __launch_bounds__(256, 2)
gemm_mma(const __nv_bfloat16* __restrict__ Ah, const __nv_bfloat16* __restrict__ Al,
         const __nv_bfloat16* __restrict__ Wh, const __nv_bfloat16* __restrict__ Wl,
         const float* __restrict__ bias, float* __restrict__ C) {
    extern __shared__ char smem[];
    uint32_t sb = smem_u32(smem);
    const int tid = threadIdx.x, lane = tid & 31, wid = tid >> 5;
    const int wm = wid & 1, wn = wid >> 1;
    const long m0 = (long)blockIdx.x * 128;
    const int n0 = blockIdx.y * 128;

    auto load_chunk = [&](int ck, int st) {
        uint32_t base = sb + st * STAGE_B;
        #pragma unroll
        for (int it = 0; it < 8; it++) {
            int idx = tid + it * 256;
            int arr = idx >> 9;
            int loc = idx & 511;
            int r = loc >> 2, seg = loc & 3;
            const __nv_bfloat16* g;
            if (arr == 0)      g = Ah + (m0 + r) * DIM + ck * 32 + seg * 8;
            else if (arr == 1) g = Al + (m0 + r) * DIM + ck * 32 + seg * 8;
            else if (arr == 2) g = Wh + (long)(n0 + r) * DIM + ck * 32 + seg * 8;
            else               g = Wl + (long)(n0 + r) * DIM + ck * 32 + seg * 8;
            cp16(base + arr * 10240 + r * 80 + seg * 16, g);
        }
        CP_COMMIT();
    };

    float acc[4][4][4];
    #pragma unroll
    for (int i = 0; i < 4; i++)
        #pragma unroll
        for (int j = 0; j < 4; j++)
            #pragma unroll
            for (int r = 0; r < 4; r++) acc[i][j][r] = 0.f;

    load_chunk(0, 0);

    const int arow = lane & 15;
    const int acolB = (lane >> 4) ? 16 : 0;
    const int brow = lane & 7;
    const int bcolB = ((lane >> 3) & 1) ? 16 : 0;

    for (int c = 0; c < 16; c++) {
        if (c + 1 < 16) { load_chunk(c + 1, (c + 1) & 1); CP_WAIT(1); }
        else            { CP_WAIT(0); }
        __syncthreads();
        uint32_t base = sb + (c & 1) * STAGE_B;
        #pragma unroll
        for (int ks = 0; ks < 2; ks++) {
            const int kb = ks * 32;
            uint32_t ah[4][4], al[4][4];
            #pragma unroll
            for (int i = 0; i < 4; i++) {
                uint32_t addr = base + (wm * 64 + i * 16 + arow) * 80 + kb + acolB;
                LDSM_X4(ah[i], addr);
                LDSM_X4(al[i], addr + 10240);
            }
            #pragma unroll
            for (int j = 0; j < 4; j++) {
                uint32_t baddr = base + 20480 + (wn * 32 + j * 8 + brow) * 80 + kb + bcolB;
                uint32_t wh2[2], wl2[2];
                LDSM_X2(wh2, baddr);
                LDSM_X2(wl2, baddr + 10240);
                #pragma unroll
                for (int i = 0; i < 4; i++) {
                    MMA16816(acc[i][j], ah[i], wh2);
                    MMA16816(acc[i][j], al[i], wh2);
                    MMA16816(acc[i][j], ah[i], wl2);
                }
            }
        }
        __syncthreads();
    }

    #pragma unroll
    for (int i = 0; i < 4; i++) {
        long r0 = m0 + wm * 64 + i * 16 + (lane >> 2);
        #pragma unroll
        for (int j = 0; j < 4; j++) {
            int col = n0 + wn * 32 + j * 8 + (lane & 3) * 2;
            float b0 = 0.f, b1 = 0.f;
            if (bias) { b0 = bias[col]; b1 = bias[col + 1]; }
            float2 v0 = { acc[i][j][0] + b0, acc[i][j][1] + b1 };
            float2 v1 = { acc[i][j][2] + b0, acc[i][j][3] + b1 };
            *(float2*)(C + r0 * DIM + col) = v0;
            *(float2*)(C + (r0 + 8) * DIM + col) = v1;
        }
    }
}

// ---------------- 16-channel half sums of kv ----------------
__global__ void halfsum_kernel(const float* __restrict__ kv) {
    int b = blockIdx.y, p0 = blockIdx.x * 32;
    int tid = threadIdx.x;
    __shared__ float sh[32][33];
    #pragma unroll
    for (int it = 0; it < 4; it++) {
        int pair = it * 256 + tid;
        int pix = pair >> 5, h32 = pair & 31;
        const float4* src = (const float4*)(kv + ((long)b*N_ + p0 + pix)*DIM + h32*16);
        float4 a = src[0], bb = src[1], cc = src[2], dd = src[3];
        sh[pix][h32] = a.x+a.y+a.z+a.w + bb.x+bb.y+bb.z+bb.w
                     + cc.x+cc.y+cc.z+cc.w + dd.x+dd.y+dd.z+dd.w;
    }
    __syncthreads();
    for (int idx = tid; idx < 1024; idx += 256) {
        int h32 = idx >> 5, pix = idx & 31;
        g_half[b][h32][p0 + pix] = sh[pix][h32];
    }
}

// ---------------- prep: pooled (from halfsums) -> fc -> single -> local ----------------
__global__ void prep_kernel(const float* __restrict__ fc0, const float* __restrict__ fc1,
                            const float* __restrict__ sg0, const float* __restrict__ sg1,
                            const float* __restrict__ lw0, const float* __restrict__ lb0,
                            const float* __restrict__ lw1, const float* __restrict__ lb1) {
    int blk = blockIdx.x;
    int br = blk >> 7, bh = blk & 127, b = bh >> 3, h = bh & 7;
    int tid = threadIdx.x;
    __shared__ float pooled[49][32], tmp[49][32], vsh[49][33];

    for (int idx = tid; idx < 49*32; idx += 256) {
        int w = idx >> 5, s = idx & 31;
        int ky = w / 7, kx = w - ky * 7;
        float sum;
        if (br == 0) {
            int ll0 = 2*s, ll1 = 2*s + 1;
            int p0 = ((ll0>>3)*7 + ky)*HW + (ll0&7)*7 + kx;
            int p1 = ((ll1>>3)*7 + ky)*HW + (ll1&7)*7 + kx;
            sum = (g_half[b][2*h][p0] + g_half[b][2*h+1][p0]
                 + g_half[b][2*h][p1] + g_half[b][2*h+1][p1]) * (1.f/64.f);
        } else {
            int ll = s >> 1;
            int p = ((ll>>2)*13 + ky*2)*HW + (ll&3)*13 + kx*2;
            sum = g_half[b][16 + 2*h + (s&1)][p] * (1.f/16.f);
        }
        pooled[w][s] = sum;
    }
    __syncthreads();
    const float* fc = br ? fc1 : fc0;
    for (int idx = tid; idx < 49*32; idx += 256) {
        int w = idx >> 5, t = idx & 31;
        float sum = 0.f;
        #pragma unroll
        for (int s = 0; s < 32; s++) sum += pooled[w][s] * fc[t*32+s];
        tmp[w][t] = sum;
    }
    __syncthreads();
    const float* sg = br ? sg1 : sg0;
    const float kscale = 0.17677669529663689f;
    for (int idx = tid; idx < 49*64; idx += 256) {
        int w = idx >> 6, j = idx & 63;
        float sum = 0.f;
        #pragma unroll
        for (int t = 0; t < 32; t++) sum += tmp[w][t] * sg[j*32+t];
        if (j < 32) g_k[(long)blk*1568 + w*32 + j] = sum * kscale;
        else        vsh[w][j-32] = sum;
    }
    __syncthreads();
    const float* lw = br ? lw1 : lw0;
    const float* lb = br ? lb1 : lb0;
    for (int idx = tid; idx < 49*32; idx += 256) {
        int w = idx >> 5, s = idx & 31;
        int wy = w / 7, wx = w - wy * 7, ch = h*S_ + s;
        float acc = vsh[w][s] + lb[ch];
        #pragma unroll
        for (int dy = 0; dy < 3; dy++) {
            int yy = wy + dy - 1;
            if (yy < 0 || yy >= 7) continue;
            #pragma unroll
            for (int dx = 0; dx < 3; dx++) {
                int xx = wx + dx - 1;
                if (xx < 0 || xx >= 7) continue;
                acc += lw[ch*9 + dy*3 + dx] * vsh[yy*7+xx][s];
            }
        }
        g_v[(long)blk*1568 + w*32 + s] = acc;
    }
}

// ---------------- attention: float4 shared reads, write bf16 splits ----------------
__global__ void attn_kernel(const float* __restrict__ q,
                            __nv_bfloat16* __restrict__ ahi, __nv_bfloat16* __restrict__ alo) {
    int blk = blockIdx.x;
    int br = blk >> 7, bh = blk & 127, b = bh >> 3, h = bh & 7;
    int tid = threadIdx.x;
    __shared__ float ksh[49][32], vsh[49][32], osh[256][33];
    const float* kp = g_k + (long)blk * 1568;
    const float* vp = g_v + (long)blk * 1568;
    for (int idx = tid; idx < 1568; idx += 256) { ((float*)ksh)[idx] = kp[idx]; ((float*)vsh)[idx] = vp[idx]; }
    __syncthreads();

    int n0 = blockIdx.y * 256, n = n0 + tid;
    if (n < N_) {
        const float* qp = q + ((long)b*N_ + n)*DIM + h*64 + br*32;
        float4 qv[8];
        #pragma unroll
        for (int v = 0; v < 8; v++) qv[v] = *(const float4*)(qp + v*4);
        float p[49], m = -1e30f;
        #pragma unroll
        for (int j = 0; j < 49; j++) {
            float s = 0.f;
            #pragma unroll
            for (int d = 0; d < 8; d++) {
                float4 kk = *(const float4*)&ksh[j][d*4];
                s += qv[d].x*kk.x + qv[d].y*kk.y + qv[d].z*kk.z + qv[d].w*kk.w;
            }
            p[j] = s; m = fmaxf(m, s);
        }
        float sum = 0.f;
        #pragma unroll
        for (int j = 0; j < 49; j++) { p[j] = __expf(p[j] - m); sum += p[j]; }
        float inv = 1.f / sum;
        float4 o[8];
        #pragma unroll
        for (int d = 0; d < 8; d++) o[d] = make_float4(0.f, 0.f, 0.f, 0.f);
        #pragma unroll
        for (int j = 0; j < 49; j++) {
            float pj = p[j];
            #pragma unroll
            for (int d = 0; d < 8; d++) {
                float4 vv = *(const float4*)&vsh[j][d*4];
                o[d].x += pj*vv.x; o[d].y += pj*vv.y;
                o[d].z += pj*vv.z; o[d].w += pj*vv.w;
            }
        }
        #pragma unroll
        for (int d = 0; d < 8; d++) {
            osh[tid][d*4+0] = o[d].x * inv; osh[tid][d*4+1] = o[d].y * inv;
            osh[tid][d*4+2] = o[d].z * inv; osh[tid][d*4+3] = o[d].w * inv;
        }
    }
    __syncthreads();
    int off = br * SD + h * S_;
    for (int idx = tid; idx < 256*16; idx += 256) {
        int qq = idx >> 4, dp = (idx & 15) * 2;
        int nn = n0 + qq;
        if (nn < N_) {
            __nv_bfloat16 h0,l0,h1,l1;
            split2(osh[qq][dp], h0, l0); split2(osh[qq][dp+1], h1, l1);
            long o = ((long)b*N_ + nn)*DIM + off + dp;
            *(__nv_bfloat162*)(ahi + o) = {h0, h1};
            *(__nv_bfloat162*)(alo + o) = {l0, l1};
        }
    }
}

// ---------------- launch ----------------
extern "C" void kernel_launch(void* const* d_in, const int* in_sizes, int n_in,
                              void* d_out, int out_size) {
    const float* x       = (const float*)d_in[0];
    const float* q_w     = (const float*)d_in[3];
    const float* kv_dw_w = (const float*)d_in[4];
    const float* kv_dw_b = (const float*)d_in[5];
    const float* kv_pw_w = (const float*)d_in[6];
    const float* kv_pw_b = (const float*)d_in[7];
    const float* fc_w0   = (const float*)d_in[8];
    const float* fc_w1   = (const float*)d_in[9];
    const float* sg_w0   = (const float*)d_in[10];
    const float* sg_w1   = (const float*)d_in[11];
    const float* lw0     = (const float*)d_in[12];
    const float* lb0     = (const float*)d_in[13];
    const float* lw1     = (const float*)d_in[14];
    const float* lb1     = (const float*)d_in[15];
    const float* proj_w  = (const float*)d_in[16];
    const float* proj_b  = (const float*)d_in[17];
    float* out = (float*)d_out;

    __nv_bfloat16 *xhi, *xlo, *d1hi, *d1lo, *a3hi, *a3lo, *wh, *wl;
    float *qb, *kvb;
    cudaGetSymbolAddress((void**)&xhi, g_xhi);   cudaGetSymbolAddress((void**)&xlo, g_xlo);
    cudaGetSymbolAddress((void**)&d1hi, g_d1hi); cudaGetSymbolAddress((void**)&d1lo, g_d1lo);
    cudaGetSymbolAddress((void**)&a3hi, g_a3hi); cudaGetSymbolAddress((void**)&a3lo, g_a3lo);
    cudaGetSymbolAddress((void**)&wh, g_wh);     cudaGetSymbolAddress((void**)&wl, g_wl);
    cudaGetSymbolAddress((void**)&qb, g_q);      cudaGetSymbolAddress((void**)&kvb, g_kv);

    cudaFuncSetAttribute(gemm_mma, cudaFuncAttributeMaxDynamicSharedMemorySize, GSMEM);

    const long WN4 = DIM * DIM / 4;
    split_kernel<<<(WN4 + 255) / 256, 256>>>(q_w,     wh,             wl,             WN4);
    split_kernel<<<(WN4 + 255) / 256, 256>>>(kv_pw_w, wh + DIM*DIM,   wl + DIM*DIM,   WN4);
    split_kernel<<<(WN4 + 255) / 256, 256>>>(proj_w,  wh + 2*DIM*DIM, wl + 2*DIM*DIM, WN4);
    dwconv_kernel<<<BN, DIM>>>(x, kv_dw_w, kv_dw_b, d1hi, d1lo, xhi, xlo);

    dim3 gg(BN / 128, DIM / 128);
    gemm_mma<<<gg, 256, GSMEM>>>(d1hi, d1lo, wh + DIM*DIM, wl + DIM*DIM, kv_pw_b, kvb);
    gemm_mma<<<gg, 256, GSMEM>>>(xhi,  xlo,  wh,           wl,           nullptr, qb);
    halfsum_kernel<<<dim3(N_ / 32, B_), 256>>>(kvb);
    prep_kernel<<<256, 256>>>(fc_w0, fc_w1, sg_w0, sg_w1, lw0, lb0, lw1, lb1);
    attn_kernel<<<dim3(256, (N_ + 255) / 256), 256>>>(qb, a3hi, a3lo);
    gemm_mma<<<gg, 256, GSMEM>>>(a3hi, a3lo, wh + 2*DIM*DIM, wl + 2*DIM*DIM, proj_b, out);
}

// round 6
// speedup vs baseline: 2.7961x; 1.0496x over previous
#include <cuda_runtime.h>
#include <cuda_bf16.h>
#include <cstdint>

#define B_    16
#define N_    3136
#define DIM   512
#define HEADS 8
#define HW    56
#define SD    256
#define S_    32
#define BN    (B_ * N_)
#define ELEMS ((long)BN * DIM)

// ---------------- scratch ----------------
__device__ __nv_bfloat16 g_xhi[ELEMS], g_xlo[ELEMS];
__device__ __nv_bfloat16 g_d1hi[ELEMS], g_d1lo[ELEMS];
__device__ __nv_bfloat16 g_a3hi[ELEMS], g_a3lo[ELEMS];
__device__ __nv_bfloat16 g_wh[3][DIM * DIM], g_wl[3][DIM * DIM];
__device__ float g_q[ELEMS];
__device__ float g_kv[ELEMS];
__device__ float g_half[B_][32][N_];
__device__ float g_k[2 * B_ * HEADS * 49 * S_];
__device__ float g_v[2 * B_ * HEADS * 49 * S_];

// ---------------- helpers ----------------
__device__ __forceinline__ uint32_t smem_u32(const void* p) {
    uint32_t a;
    asm("{ .reg .u64 t; cvta.to.shared.u64 t, %1; cvt.u32.u64 %0, t; }" : "=r"(a) : "l"(p));
    return a;
}
__device__ __forceinline__ void cp16(uint32_t d, const void* g) {
    asm volatile("cp.async.cg.shared.global [%0], [%1], 16;" :: "r"(d), "l"(g));
}
#define CP_COMMIT() asm volatile("cp.async.commit_group;" ::: "memory")
#define CP_WAIT(n)  asm volatile("cp.async.wait_group %0;" :: "n"(n) : "memory")

#define LDSM_X4(r, a) \
    asm volatile("ldmatrix.sync.aligned.m8n8.x4.shared.b16 {%0,%1,%2,%3}, [%4];" \
        : "=r"((r)[0]), "=r"((r)[1]), "=r"((r)[2]), "=r"((r)[3]) : "r"(a))
#define LDSM_X2(r, a) \
    asm volatile("ldmatrix.sync.aligned.m8n8.x2.shared.b16 {%0,%1}, [%2];" \
        : "=r"((r)[0]), "=r"((r)[1]) : "r"(a))
#define MMA16816(c, a, b) \
    asm volatile("mma.sync.aligned.m16n8k16.row.col.f32.bf16.bf16.f32 " \
        "{%0,%1,%2,%3},{%4,%5,%6,%7},{%8,%9},{%0,%1,%2,%3};" \
        : "+f"((c)[0]), "+f"((c)[1]), "+f"((c)[2]), "+f"((c)[3]) \
        : "r"((a)[0]), "r"((a)[1]), "r"((a)[2]), "r"((a)[3]), "r"((b)[0]), "r"((b)[1]))

#define FMA2(acc, a, b) \
    asm("fma.rn.f32x2 %0, %1, %2, %0;" : "+l"(acc) : "l"(a), "l"(b))
#define PACK2(d, x, y)  asm("mov.b64 %0, {%1,%2};" : "=l"(d) : "f"(x), "f"(y))
#define UNPACK2(x, y, d) asm("mov.b64 {%0,%1}, %2;" : "=f"(x), "=f"(y) : "l"(d))

__device__ __forceinline__ void split2(float v, __nv_bfloat16& h, __nv_bfloat16& l) {
    h = __float2bfloat16(v);
    l = __float2bfloat16(v - __bfloat162float(h));
}
__device__ __forceinline__ void split_store4(float4 v, __nv_bfloat16* hi, __nv_bfloat16* lo) {
    __nv_bfloat16 h0,h1,h2,h3,l0,l1,l2,l3;
    split2(v.x,h0,l0); split2(v.y,h1,l1); split2(v.z,h2,l2); split2(v.w,h3,l3);
    ((__nv_bfloat162*)hi)[0] = {h0,h1}; ((__nv_bfloat162*)hi)[1] = {h2,h3};
    ((__nv_bfloat162*)lo)[0] = {l0,l1}; ((__nv_bfloat162*)lo)[1] = {l2,l3};
}

// ---------------- weight splits: 3 matrices in one launch ----------------
__global__ void wsplit3_kernel(const float* __restrict__ s0, const float* __restrict__ s1,
                               const float* __restrict__ s2,
                               __nv_bfloat16* __restrict__ hi, __nv_bfloat16* __restrict__ lo) {
    int w = blockIdx.y;
    const float* src = w == 0 ? s0 : (w == 1 ? s1 : s2);
    long i = (long)blockIdx.x * blockDim.x + threadIdx.x;   // over float4s
    float4 v = ((const float4*)src)[i];
    long o = (long)w * DIM * DIM + i * 4;
    split_store4(v, hi + o, lo + o);
}

// ---------------- 3x3 depthwise conv + fused x split ----------------
// 128 threads x 4 channels, 8 pixels per block
__global__ void __launch_bounds__(128)
dwconv_kernel(const float* __restrict__ x, const float* __restrict__ w,
              const float* __restrict__ bias,
              __nv_bfloat16* __restrict__ ohi, __nv_bfloat16* __restrict__ olo,
              __nv_bfloat16* __restrict__ xhi, __nv_bfloat16* __restrict__ xlo) {
    int p0 = blockIdx.x * 8;
    int c4 = threadIdx.x * 4;
    float wr[9][4];
    #pragma unroll
    for (int t = 0; t < 9; t++)
        #pragma unroll
        for (int cc = 0; cc < 4; cc++) wr[t][cc] = w[(c4 + cc) * 9 + t];
    float4 b4 = *(const float4*)(bias + c4);

    #pragma unroll
    for (int pp = 0; pp < 8; pp++) {
        int p = p0 + pp;
        int b = p / N_, pix = p - b * N_;
        int hy = pix / HW, hx = pix - hy * HW;
        float4 acc = b4, xc = make_float4(0.f, 0.f, 0.f, 0.f);
        #pragma unroll
        for (int dy = 0; dy < 3; dy++) {
            int yy = hy + dy - 1;
            if (yy < 0 || yy >= HW) continue;
            #pragma unroll
            for (int dx = 0; dx < 3; dx++) {
                int xx = hx + dx - 1;
                if (xx < 0 || xx >= HW) continue;
                float4 v = *(const float4*)(x + ((long)b * N_ + yy * HW + xx) * DIM + c4);
                if (dy == 1 && dx == 1) xc = v;
                int t = dy * 3 + dx;
                acc.x += wr[t][0] * v.x; acc.y += wr[t][1] * v.y;
                acc.z += wr[t][2] * v.z; acc.w += wr[t][3] * v.w;
            }
        }
        long off = (long)p * DIM + c4;
        split_store4(acc, ohi + off, olo + off);
        split_store4(xc,  xhi + off, xlo + off);
    }
}

// ---------------------------------------------------------------------------
// mma.sync bf16x3 GEMM body; dual-source launch via blockIdx.z
// ---------------------------------------------------------------------------
#define STAGE_B  40960
#define GSMEM    (2 * STAGE_B)

struct GemmArgs {
    const __nv_bfloat16 *Ah, *Al, *Wh, *Wl;
    const float* bias;
    float* C;
};

__global__ void __launch_bounds__(256, 2)
gemm_dual(GemmArgs a0, GemmArgs a1) {
    const GemmArgs& g = blockIdx.z ? a1 : a0;
    const __nv_bfloat16* __restrict__ Ah = g.Ah;
    const __nv_bfloat16* __restrict__ Al = g.Al;
    const __nv_bfloat16* __restrict__ Wh = g.Wh;
    const __nv_bfloat16* __restrict__ Wl = g.Wl;
    const float* bias = g.bias;
    float* C = g.C;

    extern __shared__ char smem[];
    uint32_t sb = smem_u32(smem);
    const int tid = threadIdx.x, lane = tid & 31, wid = tid >> 5;
    const int wm = wid & 1, wn = wid >> 1;
    const long m0 = (long)blockIdx.x * 128;
    const int n0 = blockIdx.y * 128;

    auto load_chunk = [&](int ck, int st) {
        uint32_t base = sb + st * STAGE_B;
        #pragma unroll
        for (int it = 0; it < 8; it++) {
            int idx = tid + it * 256;
            int arr = idx >> 9;
            int loc = idx & 511;
            int r = loc >> 2, seg = loc & 3;
            const __nv_bfloat16* gp;
            if (arr == 0)      gp = Ah + (m0 + r) * DIM + ck * 32 + seg * 8;
            else if (arr == 1) gp = Al + (m0 + r) * DIM + ck * 32 + seg * 8;
            else if (arr == 2) gp = Wh + (long)(n0 + r) * DIM + ck * 32 + seg * 8;
            else               gp = Wl + (long)(n0 + r) * DIM + ck * 32 + seg * 8;
            cp16(base + arr * 10240 + r * 80 + seg * 16, gp);
        }
        CP_COMMIT();
    };

    float acc[4][4][4];
    #pragma unroll
    for (int i = 0; i < 4; i++)
        #pragma unroll
        for (int j = 0; j < 4; j++)
            #pragma unroll
            for (int r = 0; r < 4; r++) acc[i][j][r] = 0.f;

    load_chunk(0, 0);

    const int arow = lane & 15;
    const int acolB = (lane >> 4) ? 16 : 0;
    const int brow = lane & 7;
    const int bcolB = ((lane >> 3) & 1) ? 16 : 0;

    for (int c = 0; c < 16; c++) {
        if (c + 1 < 16) { load_chunk(c + 1, (c + 1) & 1); CP_WAIT(1); }
        else            { CP_WAIT(0); }
        __syncthreads();
        uint32_t base = sb + (c & 1) * STAGE_B;
        #pragma unroll
        for (int ks = 0; ks < 2; ks++) {
            const int kb = ks * 32;
            uint32_t ah[4][4], al[4][4];
            #pragma unroll
            for (int i = 0; i < 4; i++) {
                uint32_t addr = base + (wm * 64 + i * 16 + arow) * 80 + kb + acolB;
                LDSM_X4(ah[i], addr);
                LDSM_X4(al[i], addr + 10240);
            }
            #pragma unroll
            for (int j = 0; j < 4; j++) {
                uint32_t baddr = base + 20480 + (wn * 32 + j * 8 + brow) * 80 + kb + bcolB;
                uint32_t wh2[2], wl2[2];
                LDSM_X2(wh2, baddr);
                LDSM_X2(wl2, baddr + 10240);
                #pragma unroll
                for (int i = 0; i < 4; i++) {
                    MMA16816(acc[i][j], ah[i], wh2);
                    MMA16816(acc[i][j], al[i], wh2);
                    MMA16816(acc[i][j], ah[i], wl2);
                }
            }
        }
        __syncthreads();
    }

    #pragma unroll
    for (int i = 0; i < 4; i++) {
        long r0 = m0 + wm * 64 + i * 16 + (lane >> 2);
        #pragma unroll
        for (int j = 0; j < 4; j++) {
            int col = n0 + wn * 32 + j * 8 + (lane & 3) * 2;
            float b0 = 0.f, b1 = 0.f;
            if (bias) { b0 = bias[col]; b1 = bias[col + 1]; }
            float2 v0 = { acc[i][j][0] + b0, acc[i][j][1] + b1 };
            float2 v1 = { acc[i][j][2] + b0, acc[i][j][3] + b1 };
            *(float2*)(C + r0 * DIM + col) = v0;
            *(float2*)(C + (r0 + 8) * DIM + col) = v1;
        }
    }
}

// ---------------- 16-channel half sums of kv ----------------
__global__ void halfsum_kernel(const float* __restrict__ kv) {
    int b = blockIdx.y, p0 = blockIdx.x * 32;
    int tid = threadIdx.x;
    __shared__ float sh[32][33];
    #pragma unroll
    for (int it = 0; it < 4; it++) {
        int pair = it * 256 + tid;
        int pix = pair >> 5, h32 = pair & 31;
        const float4* src = (const float4*)(kv + ((long)b*N_ + p0 + pix)*DIM + h32*16);
        float4 a = src[0], bb = src[1], cc = src[2], dd = src[3];
        sh[pix][h32] = a.x+a.y+a.z+a.w + bb.x+bb.y+bb.z+bb.w
                     + cc.x+cc.y+cc.z+cc.w + dd.x+dd.y+dd.z+dd.w;
    }
    __syncthreads();
    for (int idx = tid; idx < 1024; idx += 256) {
        int h32 = idx >> 5, pix = idx & 31;
        g_half[b][h32][p0 + pix] = sh[pix][h32];
    }
}

// ---------------- prep ----------------
__global__ void prep_kernel(const float* __restrict__ fc0, const float* __restrict__ fc1,
                            const float* __restrict__ sg0, const float* __restrict__ sg1,
                            const float* __restrict__ lw0, const float* __restrict__ lb0,
                            const float* __restrict__ lw1, const float* __restrict__ lb1) {
    int blk = blockIdx.x;
    int br = blk >> 7, bh = blk & 127, b = bh >> 3, h = bh & 7;
    int tid = threadIdx.x;
    __shared__ float pooled[49][32], tmp[49][32], vsh[49][33];

    for (int idx = tid; idx < 49*32; idx += 256) {
        int w = idx >> 5, s = idx & 31;
        int ky = w / 7, kx = w - ky * 7;
        float sum;
        if (br == 0) {
            int ll0 = 2*s, ll1 = 2*s + 1;
            int p0 = ((ll0>>3)*7 + ky)*HW + (ll0&7)*7 + kx;
            int p1 = ((ll1>>3)*7 + ky)*HW + (ll1&7)*7 + kx;
            sum = (g_half[b][2*h][p0] + g_half[b][2*h+1][p0]
                 + g_half[b][2*h][p1] + g_half[b][2*h+1][p1]) * (1.f/64.f);
        } else {
            int ll = s >> 1;
            int p = ((ll>>2)*13 + ky*2)*HW + (ll&3)*13 + kx*2;
            sum = g_half[b][16 + 2*h + (s&1)][p] * (1.f/16.f);
        }
        pooled[w][s] = sum;
    }
    __syncthreads();
    const float* fc = br ? fc1 : fc0;
    for (int idx = tid; idx < 49*32; idx += 256) {
        int w = idx >> 5, t = idx & 31;
        float sum = 0.f;
        #pragma unroll
        for (int s = 0; s < 32; s++) sum += pooled[w][s] * fc[t*32+s];
        tmp[w][t] = sum;
    }
    __syncthreads();
    const float* sg = br ? sg1 : sg0;
    const float kscale = 0.17677669529663689f;
    for (int idx = tid; idx < 49*64; idx += 256) {
        int w = idx >> 6, j = idx & 63;
        float sum = 0.f;
        #pragma unroll
        for (int t = 0; t < 32; t++) sum += tmp[w][t] * sg[j*32+t];
        if (j < 32) g_k[(long)blk*1568 + w*32 + j] = sum * kscale;
        else        vsh[w][j-32] = sum;
    }
    __syncthreads();
    const float* lw = br ? lw1 : lw0;
    const float* lb = br ? lb1 : lb0;
    for (int idx = tid; idx < 49*32; idx += 256) {
        int w = idx >> 5, s = idx & 31;
        int wy = w / 7, wx = w - wy * 7, ch = h*S_ + s;
        float acc = vsh[w][s] + lb[ch];
        #pragma unroll
        for (int dy = 0; dy < 3; dy++) {
            int yy = wy + dy - 1;
            if (yy < 0 || yy >= 7) continue;
            #pragma unroll
            for (int dx = 0; dx < 3; dx++) {
                int xx = wx + dx - 1;
                if (xx < 0 || xx >= 7) continue;
                acc += lw[ch*9 + dy*3 + dx] * vsh[yy*7+xx][s];
            }
        }
        g_v[(long)blk*1568 + w*32 + s] = acc;
    }
}

// ---------------- attention: packed f32x2 FMA ----------------
__global__ void __launch_bounds__(256)
attn_kernel(const float* __restrict__ q,
            __nv_bfloat16* __restrict__ ahi, __nv_bfloat16* __restrict__ alo) {
    int blk = blockIdx.x;
    int br = blk >> 7, bh = blk & 127, b = bh >> 3, h = bh & 7;
    int tid = threadIdx.x;
    __shared__ float ksh[49][32], vsh[49][32], osh[256][33];
    const float* kp = g_k + (long)blk * 1568;
    const float* vp = g_v + (long)blk * 1568;
    for (int idx = tid; idx < 1568; idx += 256) { ((float*)ksh)[idx] = kp[idx]; ((float*)vsh)[idx] = vp[idx]; }
    __syncthreads();

    int n0 = blockIdx.y * 256, n = n0 + tid;
    if (n < N_) {
        const float* qp = q + ((long)b*N_ + n)*DIM + h*64 + br*32;
        uint64_t q2[16];
        #pragma unroll
        for (int v = 0; v < 8; v++) {
            ulonglong2 t = *(const ulonglong2*)(qp + v*4);   // float4 = 2 packed f32x2
            q2[v*2] = t.x; q2[v*2+1] = t.y;
        }
        float p[49], m = -1e30f;
        #pragma unroll
        for (int j = 0; j < 49; j++) {
            uint64_t acc2 = 0;
            #pragma unroll
            for (int d = 0; d < 8; d++) {
                ulonglong2 kk = *(const ulonglong2*)&ksh[j][d*4];
                FMA2(acc2, q2[d*2], kk.x);
                FMA2(acc2, q2[d*2+1], kk.y);
            }
            float lo, hi; UNPACK2(lo, hi, acc2);
            p[j] = lo + hi; m = fmaxf(m, p[j]);
        }
        float sum = 0.f;
        #pragma unroll
        for (int j = 0; j < 49; j++) { p[j] = __expf(p[j] - m); sum += p[j]; }
        float inv = 1.f / sum;
        uint64_t o2[16];
        #pragma unroll
        for (int d = 0; d < 16; d++) o2[d] = 0;
        #pragma unroll
        for (int j = 0; j < 49; j++) {
            uint64_t pj2; PACK2(pj2, p[j], p[j]);
            #pragma unroll
            for (int d = 0; d < 8; d++) {
                ulonglong2 vv = *(const ulonglong2*)&vsh[j][d*4];
                FMA2(o2[d*2], pj2, vv.x);
                FMA2(o2[d*2+1], pj2, vv.y);
            }
        }
        #pragma unroll
        for (int d = 0; d < 16; d++) {
            float lo, hi; UNPACK2(lo, hi, o2[d]);
            osh[tid][d*2]   = lo * inv;
            osh[tid][d*2+1] = hi * inv;
        }
    }
    __syncthreads();
    int off = br * SD + h * S_;
    for (int idx = tid; idx < 256*16; idx += 256) {
        int qq = idx >> 4, dp = (idx & 15) * 2;
        int nn = n0 + qq;
        if (nn < N_) {
            __nv_bfloat16 h0,l0,h1,l1;
            split2(osh[qq][dp], h0, l0); split2(osh[qq][dp+1], h1, l1);
            long o = ((long)b*N_ + nn)*DIM + off + dp;
            *(__nv_bfloat162*)(ahi + o) = {h0, h1};
            *(__nv_bfloat162*)(alo + o) = {l0, l1};
        }
    }
}

// ---------------- launch ----------------
extern "C" void kernel_launch(void* const* d_in, const int* in_sizes, int n_in,
                              void* d_out, int out_size) {
    const float* x       = (const float*)d_in[0];
    const float* q_w     = (const float*)d_in[3];
    const float* kv_dw_w = (const float*)d_in[4];
    const float* kv_dw_b = (const float*)d_in[5];
    const float* kv_pw_w = (const float*)d_in[6];
    const float* kv_pw_b = (const float*)d_in[7];
    const float* fc_w0   = (const float*)d_in[8];
    const float* fc_w1   = (const float*)d_in[9];
    const float* sg_w0   = (const float*)d_in[10];
    const float* sg_w1   = (const float*)d_in[11];
    const float* lw0     = (const float*)d_in[12];
    const float* lb0     = (const float*)d_in[13];
    const float* lw1     = (const float*)d_in[14];
    const float* lb1     = (const float*)d_in[15];
    const float* proj_w  = (const float*)d_in[16];
    const float* proj_b  = (const float*)d_in[17];
    float* out = (float*)d_out;

    __nv_bfloat16 *xhi, *xlo, *d1hi, *d1lo, *a3hi, *a3lo, *wh, *wl;
    float *qb, *kvb;
    cudaGetSymbolAddress((void**)&xhi, g_xhi);   cudaGetSymbolAddress((void**)&xlo, g_xlo);
    cudaGetSymbolAddress((void**)&d1hi, g_d1hi); cudaGetSymbolAddress((void**)&d1lo, g_d1lo);
    cudaGetSymbolAddress((void**)&a3hi, g_a3hi); cudaGetSymbolAddress((void**)&a3lo, g_a3lo);
    cudaGetSymbolAddress((void**)&wh, g_wh);     cudaGetSymbolAddress((void**)&wl, g_wl);
    cudaGetSymbolAddress((void**)&qb, g_q);      cudaGetSymbolAddress((void**)&kvb, g_kv);

    cudaFuncSetAttribute(gemm_dual, cudaFuncAttributeMaxDynamicSharedMemorySize, GSMEM);

    // weight splits (q_w -> slot0, kv_pw_w -> slot1, proj_w -> slot2)
    wsplit3_kernel<<<dim3(DIM*DIM/4/256, 3), 256>>>(q_w, kv_pw_w, proj_w, wh, wl);
    dwconv_kernel<<<BN/8, 128>>>(x, kv_dw_w, kv_dw_b, d1hi, d1lo, xhi, xlo);

    GemmArgs kvA { d1hi, d1lo, wh + DIM*DIM, wl + DIM*DIM, kv_pw_b, kvb };
    GemmArgs qA  { xhi,  xlo,  wh,           wl,           nullptr, qb  };
    GemmArgs pA  { a3hi, a3lo, wh + 2*DIM*DIM, wl + 2*DIM*DIM, proj_b, out };

    gemm_dual<<<dim3(BN/128, DIM/128, 2), 256, GSMEM>>>(kvA, qA);
    halfsum_kernel<<<dim3(N_/32, B_), 256>>>(kvb);
    prep_kernel<<<256, 256>>>(fc_w0, fc_w1, sg_w0, sg_w1, lw0, lb0, lw1, lb1);
    attn_kernel<<<dim3(256, (N_+255)/256), 256>>>(qb, a3hi, a3lo);
    gemm_dual<<<dim3(BN/128, DIM/128, 1), 256, GSMEM>>>(pA, pA);
}

// round 7
// speedup vs baseline: 4.6651x; 1.6684x over previous
#include <cuda_runtime.h>
#include <cuda_fp16.h>
#include <cuda_bf16.h>
#include <cstdint>

#define B_    16
#define N_    3136
#define DIM   512
#define HEADS 8
#define HW    56
#define SD    256
#define S_    32
#define BN    (B_ * N_)
#define ELEMS ((long)BN * DIM)

// ---------------- scratch ----------------
__device__ __half g_x16[ELEMS];          // fp16 x
__device__ __half g_d116[ELEMS];         // fp16 dwconv out
__device__ __half g_a316[ELEMS];         // fp16 attn out
__device__ __half g_w16[3][DIM * DIM];   // fp16 weights: q, pw, proj
__device__ float g_q[ELEMS];
__device__ float g_kv[ELEMS];
__device__ float g_half[B_][32][N_];
__device__ float g_k[2 * B_ * HEADS * 49 * S_];
__device__ float g_v[2 * B_ * HEADS * 49 * S_];

// ---------------- helpers ----------------
__device__ __forceinline__ uint32_t smem_u32(const void* p) {
    uint32_t a;
    asm("{ .reg .u64 t; cvta.to.shared.u64 t, %1; cvt.u32.u64 %0, t; }" : "=r"(a) : "l"(p));
    return a;
}
__device__ __forceinline__ void cp16(uint32_t d, const void* g) {
    asm volatile("cp.async.cg.shared.global [%0], [%1], 16;" :: "r"(d), "l"(g));
}
#define CP_COMMIT() asm volatile("cp.async.commit_group;" ::: "memory")
#define CP_WAIT(n)  asm volatile("cp.async.wait_group %0;" :: "n"(n) : "memory")

#define LDSM_X4(r, a) \
    asm volatile("ldmatrix.sync.aligned.m8n8.x4.shared.b16 {%0,%1,%2,%3}, [%4];" \
        : "=r"((r)[0]), "=r"((r)[1]), "=r"((r)[2]), "=r"((r)[3]) : "r"(a))
#define LDSM_X2(r, a) \
    asm volatile("ldmatrix.sync.aligned.m8n8.x2.shared.b16 {%0,%1}, [%2];" \
        : "=r"((r)[0]), "=r"((r)[1]) : "r"(a))
#define MMA16816F16(c, a, b) \
    asm volatile("mma.sync.aligned.m16n8k16.row.col.f32.f16.f16.f32 " \
        "{%0,%1,%2,%3},{%4,%5,%6,%7},{%8,%9},{%0,%1,%2,%3};" \
        : "+f"((c)[0]), "+f"((c)[1]), "+f"((c)[2]), "+f"((c)[3]) \
        : "r"((a)[0]), "r"((a)[1]), "r"((a)[2]), "r"((a)[3]), "r"((b)[0]), "r"((b)[1]))

#define FMA2(acc, a, b) \
    asm("fma.rn.f32x2 %0, %1, %2, %0;" : "+l"(acc) : "l"(a), "l"(b))
#define PACK2(d, x, y)  asm("mov.b64 %0, {%1,%2};" : "=l"(d) : "f"(x), "f"(y))
#define UNPACK2(x, y, d) asm("mov.b64 {%0,%1}, %2;" : "=f"(x), "=f"(y) : "l"(d))

__device__ __forceinline__ void store_h4(float4 v, __half* dst) {
    __half2* d = (__half2*)dst;
    d[0] = __floats2half2_rn(v.x, v.y);
    d[1] = __floats2half2_rn(v.z, v.w);
}

// ---------------- weight conversion: 3 matrices in one launch ----------------
__global__ void wsplit3_kernel(const float* __restrict__ s0, const float* __restrict__ s1,
                               const float* __restrict__ s2, __half* __restrict__ out) {
    int w = blockIdx.y;
    const float* src = w == 0 ? s0 : (w == 1 ? s1 : s2);
    long i = (long)blockIdx.x * blockDim.x + threadIdx.x;   // over float4s
    float4 v = ((const float4*)src)[i];
    store_h4(v, out + (long)w * DIM * DIM + i * 4);
}

// ---------------- 3x3 depthwise conv + fused x convert ----------------
__global__ void __launch_bounds__(128)
dwconv_kernel(const float* __restrict__ x, const float* __restrict__ w,
              const float* __restrict__ bias,
              __half* __restrict__ o16, __half* __restrict__ x16) {
    int p0 = blockIdx.x * 8;
    int c4 = threadIdx.x * 4;
    float wr[9][4];
    #pragma unroll
    for (int t = 0; t < 9; t++)
        #pragma unroll
        for (int cc = 0; cc < 4; cc++) wr[t][cc] = w[(c4 + cc) * 9 + t];
    float4 b4 = *(const float4*)(bias + c4);

    #pragma unroll
    for (int pp = 0; pp < 8; pp++) {
        int p = p0 + pp;
        int b = p / N_, pix = p - b * N_;
        int hy = pix / HW, hx = pix - hy * HW;
        float4 acc = b4, xc = make_float4(0.f, 0.f, 0.f, 0.f);
        #pragma unroll
        for (int dy = 0; dy < 3; dy++) {
            int yy = hy + dy - 1;
            if (yy < 0 || yy >= HW) continue;
            #pragma unroll
            for (int dx = 0; dx < 3; dx++) {
                int xx = hx + dx - 1;
                if (xx < 0 || xx >= HW) continue;
                float4 v = *(const float4*)(x + ((long)b * N_ + yy * HW + xx) * DIM + c4);
                if (dy == 1 && dx == 1) xc = v;
                int t = dy * 3 + dx;
                acc.x += wr[t][0] * v.x; acc.y += wr[t][1] * v.y;
                acc.z += wr[t][2] * v.z; acc.w += wr[t][3] * v.w;
            }
        }
        long off = (long)p * DIM + c4;
        store_h4(acc, o16 + off);
        store_h4(xc,  x16 + off);
    }
}

// ---------------------------------------------------------------------------
// fp16 mma.sync GEMM: C[M,512] = A @ W^T (+bias)
// block 128x128, 8 warps, warp tile 64x32, K-chunk 32, 2-stage cp.async
// Stage: A 128x(32+8pad) fp16 (80B stride) + W same = 20480 B
// ---------------------------------------------------------------------------
#define STAGE_B  20480
#define GSMEM    (2 * STAGE_B)

struct GemmArgs {
    const __half *A, *W;
    const float* bias;
    float* C;
};

__global__ void __launch_bounds__(256, 2)
gemm_dual(GemmArgs a0, GemmArgs a1) {
    const GemmArgs& g = blockIdx.z ? a1 : a0;
    const __half* __restrict__ A = g.A;
    const __half* __restrict__ W = g.W;
    const float* bias = g.bias;
    float* C = g.C;

    extern __shared__ char smem[];
    uint32_t sb = smem_u32(smem);
    const int tid = threadIdx.x, lane = tid & 31, wid = tid >> 5;
    const int wm = wid & 1, wn = wid >> 1;
    const long m0 = (long)blockIdx.x * 128;
    const int n0 = blockIdx.y * 128;

    auto load_chunk = [&](int ck, int st) {
        uint32_t base = sb + st * STAGE_B;
        #pragma unroll
        for (int it = 0; it < 4; it++) {
            int idx = tid + it * 256;        // 0..1023
            int arr = idx >> 9;              // 0:A 1:W
            int loc = idx & 511;
            int r = loc >> 2, seg = loc & 3;
            const __half* gp = arr == 0
                ? A + (m0 + r) * DIM + ck * 32 + seg * 8
                : W + (long)(n0 + r) * DIM + ck * 32 + seg * 8;
            cp16(base + arr * 10240 + r * 80 + seg * 16, gp);
        }
        CP_COMMIT();
    };

    float acc[4][4][4];
    #pragma unroll
    for (int i = 0; i < 4; i++)
        #pragma unroll
        for (int j = 0; j < 4; j++)
            #pragma unroll
            for (int r = 0; r < 4; r++) acc[i][j][r] = 0.f;

    load_chunk(0, 0);

    const int arow = lane & 15;
    const int acolB = (lane >> 4) ? 16 : 0;
    const int brow = lane & 7;
    const int bcolB = ((lane >> 3) & 1) ? 16 : 0;

    for (int c = 0; c < 16; c++) {
        if (c + 1 < 16) { load_chunk(c + 1, (c + 1) & 1); CP_WAIT(1); }
        else            { CP_WAIT(0); }
        __syncthreads();
        uint32_t base = sb + (c & 1) * STAGE_B;
        #pragma unroll
        for (int ks = 0; ks < 2; ks++) {
            const int kb = ks * 32;
            uint32_t ah[4][4];
            #pragma unroll
            for (int i = 0; i < 4; i++) {
                uint32_t addr = base + (wm * 64 + i * 16 + arow) * 80 + kb + acolB;
                LDSM_X4(ah[i], addr);
            }
            #pragma unroll
            for (int j = 0; j < 4; j++) {
                uint32_t baddr = base + 10240 + (wn * 32 + j * 8 + brow) * 80 + kb + bcolB;
                uint32_t wh2[2];
                LDSM_X2(wh2, baddr);
                #pragma unroll
                for (int i = 0; i < 4; i++)
                    MMA16816F16(acc[i][j], ah[i], wh2);
            }
        }
        __syncthreads();
    }

    #pragma unroll
    for (int i = 0; i < 4; i++) {
        long r0 = m0 + wm * 64 + i * 16 + (lane >> 2);
        #pragma unroll
        for (int j = 0; j < 4; j++) {
            int col = n0 + wn * 32 + j * 8 + (lane & 3) * 2;
            float b0 = 0.f, b1 = 0.f;
            if (bias) { b0 = bias[col]; b1 = bias[col + 1]; }
            float2 v0 = { acc[i][j][0] + b0, acc[i][j][1] + b1 };
            float2 v1 = { acc[i][j][2] + b0, acc[i][j][3] + b1 };
            *(float2*)(C + r0 * DIM + col) = v0;
            *(float2*)(C + (r0 + 8) * DIM + col) = v1;
        }
    }
}

// ---------------- 16-channel half sums of kv ----------------
__global__ void halfsum_kernel(const float* __restrict__ kv) {
    int b = blockIdx.y, p0 = blockIdx.x * 32;
    int tid = threadIdx.x;
    __shared__ float sh[32][33];
    #pragma unroll
    for (int it = 0; it < 4; it++) {
        int pair = it * 256 + tid;
        int pix = pair >> 5, h32 = pair & 31;
        const float4* src = (const float4*)(kv + ((long)b*N_ + p0 + pix)*DIM + h32*16);
        float4 a = src[0], bb = src[1], cc = src[2], dd = src[3];
        sh[pix][h32] = a.x+a.y+a.z+a.w + bb.x+bb.y+bb.z+bb.w
                     + cc.x+cc.y+cc.z+cc.w + dd.x+dd.y+dd.z+dd.w;
    }
    __syncthreads();
    for (int idx = tid; idx < 1024; idx += 256) {
        int h32 = idx >> 5, pix = idx & 31;
        g_half[b][h32][p0 + pix] = sh[pix][h32];
    }
}

// ---------------- prep ----------------
__global__ void prep_kernel(const float* __restrict__ fc0, const float* __restrict__ fc1,
                            const float* __restrict__ sg0, const float* __restrict__ sg1,
                            const float* __restrict__ lw0, const float* __restrict__ lb0,
                            const float* __restrict__ lw1, const float* __restrict__ lb1) {
    int blk = blockIdx.x;
    int br = blk >> 7, bh = blk & 127, b = bh >> 3, h = bh & 7;
    int tid = threadIdx.x;
    __shared__ float pooled[49][32], tmp[49][32], vsh[49][33];

    for (int idx = tid; idx < 49*32; idx += 256) {
        int w = idx >> 5, s = idx & 31;
        int ky = w / 7, kx = w - ky * 7;
        float sum;
        if (br == 0) {
            int ll0 = 2*s, ll1 = 2*s + 1;
            int p0 = ((ll0>>3)*7 + ky)*HW + (ll0&7)*7 + kx;
            int p1 = ((ll1>>3)*7 + ky)*HW + (ll1&7)*7 + kx;
            sum = (g_half[b][2*h][p0] + g_half[b][2*h+1][p0]
                 + g_half[b][2*h][p1] + g_half[b][2*h+1][p1]) * (1.f/64.f);
        } else {
            int ll = s >> 1;
            int p = ((ll>>2)*13 + ky*2)*HW + (ll&3)*13 + kx*2;
            sum = g_half[b][16 + 2*h + (s&1)][p] * (1.f/16.f);
        }
        pooled[w][s] = sum;
    }
    __syncthreads();
    const float* fc = br ? fc1 : fc0;
    for (int idx = tid; idx < 49*32; idx += 256) {
        int w = idx >> 5, t = idx & 31;
        float sum = 0.f;
        #pragma unroll
        for (int s = 0; s < 32; s++) sum += pooled[w][s] * fc[t*32+s];
        tmp[w][t] = sum;
    }
    __syncthreads();
    const float* sg = br ? sg1 : sg0;
    const float kscale = 0.17677669529663689f;
    for (int idx = tid; idx < 49*64; idx += 256) {
        int w = idx >> 6, j = idx & 63;
        float sum = 0.f;
        #pragma unroll
        for (int t = 0; t < 32; t++) sum += tmp[w][t] * sg[j*32+t];
        if (j < 32) g_k[(long)blk*1568 + w*32 + j] = sum * kscale;
        else        vsh[w][j-32] = sum;
    }
    __syncthreads();
    const float* lw = br ? lw1 : lw0;
    const float* lb = br ? lb1 : lb0;
    for (int idx = tid; idx < 49*32; idx += 256) {
        int w = idx >> 5, s = idx & 31;
        int wy = w / 7, wx = w - wy * 7, ch = h*S_ + s;
        float acc = vsh[w][s] + lb[ch];
        #pragma unroll
        for (int dy = 0; dy < 3; dy++) {
            int yy = wy + dy - 1;
            if (yy < 0 || yy >= 7) continue;
            #pragma unroll
            for (int dx = 0; dx < 3; dx++) {
                int xx = wx + dx - 1;
                if (xx < 0 || xx >= 7) continue;
                acc += lw[ch*9 + dy*3 + dx] * vsh[yy*7+xx][s];
            }
        }
        g_v[(long)blk*1568 + w*32 + s] = acc;
    }
}

// ---------------- attention: packed f32x2 FMA, fp16 epilogue ----------------
__global__ void __launch_bounds__(256)
attn_kernel(const float* __restrict__ q, __half* __restrict__ a16) {
    int blk = blockIdx.x;
    int br = blk >> 7, bh = blk & 127, b = bh >> 3, h = bh & 7;
    int tid = threadIdx.x;
    __shared__ float ksh[49][32], vsh[49][32], osh[256][33];
    const float* kp = g_k + (long)blk * 1568;
    const float* vp = g_v + (long)blk * 1568;
    for (int idx = tid; idx < 1568; idx += 256) { ((float*)ksh)[idx] = kp[idx]; ((float*)vsh)[idx] = vp[idx]; }
    __syncthreads();

    int n0 = blockIdx.y * 256, n = n0 + tid;
    if (n < N_) {
        const float* qp = q + ((long)b*N_ + n)*DIM + h*64 + br*32;
        uint64_t q2[16];
        #pragma unroll
        for (int v = 0; v < 8; v++) {
            ulonglong2 t = *(const ulonglong2*)(qp + v*4);
            q2[v*2] = t.x; q2[v*2+1] = t.y;
        }
        float p[49], m = -1e30f;
        #pragma unroll
        for (int j = 0; j < 49; j++) {
            uint64_t acc2 = 0;
            #pragma unroll
            for (int d = 0; d < 8; d++) {
                ulonglong2 kk = *(const ulonglong2*)&ksh[j][d*4];
                FMA2(acc2, q2[d*2], kk.x);
                FMA2(acc2, q2[d*2+1], kk.y);
            }
            float lo, hi; UNPACK2(lo, hi, acc2);
            p[j] = lo + hi; m = fmaxf(m, p[j]);
        }
        float sum = 0.f;
        #pragma unroll
        for (int j = 0; j < 49; j++) { p[j] = __expf(p[j] - m); sum += p[j]; }
        float inv = 1.f / sum;
        uint64_t o2[16];
        #pragma unroll
        for (int d = 0; d < 16; d++) o2[d] = 0;
        #pragma unroll
        for (int j = 0; j < 49; j++) {
            uint64_t pj2; PACK2(pj2, p[j], p[j]);
            #pragma unroll
            for (int d = 0; d < 8; d++) {
                ulonglong2 vv = *(const ulonglong2*)&vsh[j][d*4];
                FMA2(o2[d*2], pj2, vv.x);
                FMA2(o2[d*2+1], pj2, vv.y);
            }
        }
        #pragma unroll
        for (int d = 0; d < 16; d++) {
            float lo, hi; UNPACK2(lo, hi, o2[d]);
            osh[tid][d*2]   = lo * inv;
            osh[tid][d*2+1] = hi * inv;
        }
    }
    __syncthreads();
    int off = br * SD + h * S_;
    for (int idx = tid; idx < 256*16; idx += 256) {
        int qq = idx >> 4, dp = (idx & 15) * 2;
        int nn = n0 + qq;
        if (nn < N_) {
            long o = ((long)b*N_ + nn)*DIM + off + dp;
            *(__half2*)(a16 + o) = __floats2half2_rn(osh[qq][dp], osh[qq][dp+1]);
        }
    }
}

// ---------------- launch ----------------
extern "C" void kernel_launch(void* const* d_in, const int* in_sizes, int n_in,
                              void* d_out, int out_size) {
    const float* x       = (const float*)d_in[0];
    const float* q_w     = (const float*)d_in[3];
    const float* kv_dw_w = (const float*)d_in[4];
    const float* kv_dw_b = (const float*)d_in[5];
    const float* kv_pw_w = (const float*)d_in[6];
    const float* kv_pw_b = (const float*)d_in[7];
    const float* fc_w0   = (const float*)d_in[8];
    const float* fc_w1   = (const float*)d_in[9];
    const float* sg_w0   = (const float*)d_in[10];
    const float* sg_w1   = (const float*)d_in[11];
    const float* lw0     = (const float*)d_in[12];
    const float* lb0     = (const float*)d_in[13];
    const float* lw1     = (const float*)d_in[14];
    const float* lb1     = (const float*)d_in[15];
    const float* proj_w  = (const float*)d_in[16];
    const float* proj_b  = (const float*)d_in[17];
    float* out = (float*)d_out;

    __half *x16, *d116, *a316, *w16;
    float *qb, *kvb;
    cudaGetSymbolAddress((void**)&x16, g_x16);
    cudaGetSymbolAddress((void**)&d116, g_d116);
    cudaGetSymbolAddress((void**)&a316, g_a316);
    cudaGetSymbolAddress((void**)&w16, g_w16);
    cudaGetSymbolAddress((void**)&qb, g_q);
    cudaGetSymbolAddress((void**)&kvb, g_kv);

    cudaFuncSetAttribute(gemm_dual, cudaFuncAttributeMaxDynamicSharedMemorySize, GSMEM);

    wsplit3_kernel<<<dim3(DIM*DIM/4/256, 3), 256>>>(q_w, kv_pw_w, proj_w, w16);
    dwconv_kernel<<<BN/8, 128>>>(x, kv_dw_w, kv_dw_b, d116, x16);

    GemmArgs kvA { d116, w16 + DIM*DIM,   kv_pw_b, kvb };
    GemmArgs qA  { x16,  w16,             nullptr, qb  };
    GemmArgs pA  { a316, w16 + 2*DIM*DIM, proj_b,  out };

    gemm_dual<<<dim3(BN/128, DIM/128, 2), 256, GSMEM>>>(kvA, qA);
    halfsum_kernel<<<dim3(N_/32, B_), 256>>>(kvb);
    prep_kernel<<<256, 256>>>(fc_w0, fc_w1, sg_w0, sg_w1, lw0, lb0, lw1, lb1);
    attn_kernel<<<dim3(256, (N_+255)/256), 256>>>(qb, a316);
    gemm_dual<<<dim3(BN/128, DIM/128, 1), 256, GSMEM>>>(pA, pA);
}

// round 13
// speedup vs baseline: 5.0379x; 1.0799x over previous
#include <cuda_runtime.h>
#include <cuda_fp16.h>
#include <cstdint>

#define B_    16
#define N_    3136
#define DIM   512
#define HEADS 8
#define HW    56
#define SD    256
#define S_    32
#define BN    (B_ * N_)
#define ELEMS ((long)BN * DIM)

// ---------------- scratch ----------------
__device__ __half g_x16[ELEMS];          // fp16 x
__device__ __half g_d116[ELEMS];         // fp16 dwconv out
__device__ __half g_a316[ELEMS];         // fp16 attn out
__device__ __half g_q16[ELEMS];          // fp16 q (GEMM out)
__device__ __half g_w16[3][DIM * DIM];   // fp16 weights: q, pw, proj
__device__ float g_half[B_][32][N_];     // 16-ch sums of kv (from GEMM epilogue)
__device__ float g_k[2 * B_ * HEADS * 49 * S_];
__device__ float g_v[2 * B_ * HEADS * 49 * S_];

// ---------------- helpers ----------------
__device__ __forceinline__ uint32_t smem_u32(const void* p) {
    uint32_t a;
    asm("{ .reg .u64 t; cvta.to.shared.u64 t, %1; cvt.u32.u64 %0, t; }" : "=r"(a) : "l"(p));
    return a;
}
__device__ __forceinline__ void cp16(uint32_t d, const void* g) {
    asm volatile("cp.async.cg.shared.global [%0], [%1], 16;" :: "r"(d), "l"(g));
}
#define CP_COMMIT() asm volatile("cp.async.commit_group;" ::: "memory")
#define CP_WAIT(n)  asm volatile("cp.async.wait_group %0;" :: "n"(n) : "memory")

#define LDSM_X4(r, a) \
    asm volatile("ldmatrix.sync.aligned.m8n8.x4.shared.b16 {%0,%1,%2,%3}, [%4];" \
        : "=r"((r)[0]), "=r"((r)[1]), "=r"((r)[2]), "=r"((r)[3]) : "r"(a))
#define LDSM_X2(r, a) \
    asm volatile("ldmatrix.sync.aligned.m8n8.x2.shared.b16 {%0,%1}, [%2];" \
        : "=r"((r)[0]), "=r"((r)[1]) : "r"(a))
#define MMA16816F16(c, a, b) \
    asm volatile("mma.sync.aligned.m16n8k16.row.col.f32.f16.f16.f32 " \
        "{%0,%1,%2,%3},{%4,%5,%6,%7},{%8,%9},{%0,%1,%2,%3};" \
        : "+f"((c)[0]), "+f"((c)[1]), "+f"((c)[2]), "+f"((c)[3]) \
        : "r"((a)[0]), "r"((a)[1]), "r"((a)[2]), "r"((a)[3]), "r"((b)[0]), "r"((b)[1]))

#define FMA2(acc, a, b) \
    asm("fma.rn.f32x2 %0, %1, %2, %0;" : "+l"(acc) : "l"(a), "l"(b))
#define PACK2(d, x, y)  asm("mov.b64 %0, {%1,%2};" : "=l"(d) : "f"(x), "f"(y))
#define UNPACK2(x, y, d) asm("mov.b64 {%0,%1}, %2;" : "=f"(x), "=f"(y) : "l"(d))

__device__ __forceinline__ void store_h4(float4 v, __half* dst) {
    __half2* d = (__half2*)dst;
    d[0] = __floats2half2_rn(v.x, v.y);
    d[1] = __floats2half2_rn(v.z, v.w);
}

// ---------------- weight conversion: 3 matrices in one launch ----------------
__global__ void wsplit3_kernel(const float* __restrict__ s0, const float* __restrict__ s1,
                               const float* __restrict__ s2, __half* __restrict__ out) {
    int w = blockIdx.y;
    const float* src = w == 0 ? s0 : (w == 1 ? s1 : s2);
    long i = (long)blockIdx.x * blockDim.x + threadIdx.x;
    float4 v = ((const float4*)src)[i];
    store_h4(v, out + (long)w * DIM * DIM + i * 4);
}

// ---------------- 3x3 depthwise conv + fused x convert ----------------
__global__ void __launch_bounds__(128)
dwconv_kernel(const float* __restrict__ x, const float* __restrict__ w,
              const float* __restrict__ bias,
              __half* __restrict__ o16, __half* __restrict__ x16) {
    int p0 = blockIdx.x * 8;
    int c4 = threadIdx.x * 4;
    float wr[9][4];
    #pragma unroll
    for (int t = 0; t < 9; t++)
        #pragma unroll
        for (int cc = 0; cc < 4; cc++) wr[t][cc] = w[(c4 + cc) * 9 + t];
    float4 b4 = *(const float4*)(bias + c4);

    #pragma unroll
    for (int pp = 0; pp < 8; pp++) {
        int p = p0 + pp;
        int b = p / N_, pix = p - b * N_;
        int hy = pix / HW, hx = pix - hy * HW;
        float4 acc = b4, xc = make_float4(0.f, 0.f, 0.f, 0.f);
        #pragma unroll
        for (int dy = 0; dy < 3; dy++) {
            int yy = hy + dy - 1;
            if (yy < 0 || yy >= HW) continue;
            #pragma unroll
            for (int dx = 0; dx < 3; dx++) {
                int xx = hx + dx - 1;
                if (xx < 0 || xx >= HW) continue;
                float4 v = *(const float4*)(x + ((long)b * N_ + yy * HW + xx) * DIM + c4);
                if (dy == 1 && dx == 1) xc = v;
                int t = dy * 3 + dx;
                acc.x += wr[t][0] * v.x; acc.y += wr[t][1] * v.y;
                acc.z += wr[t][2] * v.z; acc.w += wr[t][3] * v.w;
            }
        }
        long off = (long)p * DIM + c4;
        store_h4(acc, o16 + off);
        store_h4(xc,  x16 + off);
    }
}

// ---------------------------------------------------------------------------
// fp16 mma.sync GEMM — 2-stage mainloop (known good); epilogue modes:
//   mode 0: fp32 C (+bias)   mode 1: fp16 C16   mode 2: 16-ch group sums -> g_half
// ---------------------------------------------------------------------------
#define STAGE_B  20480
#define GSMEM    (2 * STAGE_B)

struct GemmArgs {
    const __half *A, *W;
    const float* bias;
    float* C;
    __half* C16;
    int mode;
};

__global__ void __launch_bounds__(256, 2)
gemm_dual(GemmArgs a0, GemmArgs a1) {
    const GemmArgs& g = blockIdx.z ? a1 : a0;
    const __half* __restrict__ A = g.A;
    const __half* __restrict__ W = g.W;
    const float* bias = g.bias;

    extern __shared__ char smem[];
    uint32_t sb = smem_u32(smem);
    const int tid = threadIdx.x, lane = tid & 31, wid = tid >> 5;
    const int wm = wid & 1, wn = wid >> 1;
    const long m0 = (long)blockIdx.x * 128;
    const int n0 = blockIdx.y * 128;

    auto load_chunk = [&](int ck, int st) {
        uint32_t base = sb + st * STAGE_B;
        #pragma unroll
        for (int it = 0; it < 4; it++) {
            int idx = tid + it * 256;
            int arr = idx >> 9;
            int loc = idx & 511;
            int r = loc >> 2, seg = loc & 3;
            const __half* gp = arr == 0
                ? A + (m0 + r) * DIM + ck * 32 + seg * 8
                : W + (long)(n0 + r) * DIM + ck * 32 + seg * 8;
            cp16(base + arr * 10240 + r * 80 + seg * 16, gp);
        }
        CP_COMMIT();
    };

    float acc[4][4][4];
    #pragma unroll
    for (int i = 0; i < 4; i++)
        #pragma unroll
        for (int j = 0; j < 4; j++)
            #pragma unroll
            for (int r = 0; r < 4; r++) acc[i][j][r] = 0.f;

    load_chunk(0, 0);

    const int arow = lane & 15;
    const int acolB = (lane >> 4) ? 16 : 0;
    const int brow = lane & 7;
    const int bcolB = ((lane >> 3) & 1) ? 16 : 0;

    for (int c = 0; c < 16; c++) {
        if (c + 1 < 16) { load_chunk(c + 1, (c + 1) & 1); CP_WAIT(1); }
        else            { CP_WAIT(0); }
        __syncthreads();
        uint32_t base = sb + (c & 1) * STAGE_B;
        #pragma unroll
        for (int ks = 0; ks < 2; ks++) {
            const int kb = ks * 32;
            uint32_t ah[4][4];
            #pragma unroll
            for (int i = 0; i < 4; i++) {
                uint32_t addr = base + (wm * 64 + i * 16 + arow) * 80 + kb + acolB;
                LDSM_X4(ah[i], addr);
            }
            #pragma unroll
            for (int j = 0; j < 4; j++) {
                uint32_t baddr = base + 10240 + (wn * 32 + j * 8 + brow) * 80 + kb + bcolB;
                uint32_t wh2[2];
                LDSM_X2(wh2, baddr);
                #pragma unroll
                for (int i = 0; i < 4; i++)
                    MMA16816F16(acc[i][j], ah[i], wh2);
            }
        }
        __syncthreads();
    }

    if (g.mode == 2) {
        // 16-channel group sums -> g_half[b][group][pix]; bias folded in
        #pragma unroll
        for (int i = 0; i < 4; i++) {
            float gA0 = 0.f, gA8 = 0.f, gB0 = 0.f, gB8 = 0.f;
            #pragma unroll
            for (int j = 0; j < 4; j++) {
                int col = n0 + wn * 32 + j * 8 + (lane & 3) * 2;
                float b0 = bias[col], b1 = bias[col + 1];
                float s0 = acc[i][j][0] + b0 + acc[i][j][1] + b1;
                float s8 = acc[i][j][2] + b0 + acc[i][j][3] + b1;
                if (j < 2) { gA0 += s0; gA8 += s8; }
                else       { gB0 += s0; gB8 += s8; }
            }
            #pragma unroll
            for (int d = 1; d <= 2; d <<= 1) {
                gA0 += __shfl_xor_sync(0xffffffffu, gA0, d);
                gA8 += __shfl_xor_sync(0xffffffffu, gA8, d);
                gB0 += __shfl_xor_sync(0xffffffffu, gB0, d);
                gB8 += __shfl_xor_sync(0xffffffffu, gB8, d);
            }
            if ((lane & 3) == 0) {
                int g0 = (n0 + wn * 32) >> 4, g1 = g0 + 1;
                long m = m0 + wm * 64 + i * 16 + (lane >> 2);
                int bb = (int)(m / N_), pix = (int)(m - (long)bb * N_);
                g_half[bb][g0][pix] = gA0;
                g_half[bb][g1][pix] = gB0;
                m += 8; bb = (int)(m / N_); pix = (int)(m - (long)bb * N_);
                g_half[bb][g0][pix] = gA8;
                g_half[bb][g1][pix] = gB8;
            }
        }
    } else if (g.mode == 1) {
        __half* C16 = g.C16;
        #pragma unroll
        for (int i = 0; i < 4; i++) {
            long r0 = m0 + wm * 64 + i * 16 + (lane >> 2);
            #pragma unroll
            for (int j = 0; j < 4; j++) {
                int col = n0 + wn * 32 + j * 8 + (lane & 3) * 2;
                *(__half2*)(C16 + r0 * DIM + col) =
                    __floats2half2_rn(acc[i][j][0], acc[i][j][1]);
                *(__half2*)(C16 + (r0 + 8) * DIM + col) =
                    __floats2half2_rn(acc[i][j][2], acc[i][j][3]);
            }
        }
    } else {
        float* C = g.C;
        #pragma unroll
        for (int i = 0; i < 4; i++) {
            long r0 = m0 + wm * 64 + i * 16 + (lane >> 2);
            #pragma unroll
            for (int j = 0; j < 4; j++) {
                int col = n0 + wn * 32 + j * 8 + (lane & 3) * 2;
                float b0 = bias ? bias[col] : 0.f, b1 = bias ? bias[col + 1] : 0.f;
                float2 v0 = { acc[i][j][0] + b0, acc[i][j][1] + b1 };
                float2 v1 = { acc[i][j][2] + b0, acc[i][j][3] + b1 };
                *(float2*)(C + r0 * DIM + col) = v0;
                *(float2*)(C + (r0 + 8) * DIM + col) = v1;
            }
        }
    }
}

// ---------------- prep ----------------
__global__ void prep_kernel(const float* __restrict__ fc0, const float* __restrict__ fc1,
                            const float* __restrict__ sg0, const float* __restrict__ sg1,
                            const float* __restrict__ lw0, const float* __restrict__ lb0,
                            const float* __restrict__ lw1, const float* __restrict__ lb1) {
    int blk = blockIdx.x;
    int br = blk >> 7, bh = blk & 127, b = bh >> 3, h = bh & 7;
    int tid = threadIdx.x;
    __shared__ float pooled[49][32], tmp[49][32], vsh[49][33];

    for (int idx = tid; idx < 49*32; idx += 256) {
        int w = idx >> 5, s = idx & 31;
        int ky = w / 7, kx = w - ky * 7;
        float sum;
        if (br == 0) {
            int ll0 = 2*s, ll1 = 2*s + 1;
            int p0 = ((ll0>>3)*7 + ky)*HW + (ll0&7)*7 + kx;
            int p1 = ((ll1>>3)*7 + ky)*HW + (ll1&7)*7 + kx;
            sum = (g_half[b][2*h][p0] + g_half[b][2*h+1][p0]
                 + g_half[b][2*h][p1] + g_half[b][2*h+1][p1]) * (1.f/64.f);
        } else {
            int ll = s >> 1;
            int p = ((ll>>2)*13 + ky*2)*HW + (ll&3)*13 + kx*2;
            sum = g_half[b][16 + 2*h + (s&1)][p] * (1.f/16.f);
        }
        pooled[w][s] = sum;
    }
    __syncthreads();
    const float* fc = br ? fc1 : fc0;
    for (int idx = tid; idx < 49*32; idx += 256) {
        int w = idx >> 5, t = idx & 31;
        float sum = 0.f;
        #pragma unroll
        for (int s = 0; s < 32; s++) sum += pooled[w][s] * fc[t*32+s];
        tmp[w][t] = sum;
    }
    __syncthreads();
    const float* sg = br ? sg1 : sg0;
    const float kscale = 0.17677669529663689f;
    for (int idx = tid; idx < 49*64; idx += 256) {
        int w = idx >> 6, j = idx & 63;
        float sum = 0.f;
        #pragma unroll
        for (int t = 0; t < 32; t++) sum += tmp[w][t] * sg[j*32+t];
        if (j < 32) g_k[(long)blk*1568 + w*32 + j] = sum * kscale;
        else        vsh[w][j-32] = sum;
    }
    __syncthreads();
    const float* lw = br ? lw1 : lw0;
    const float* lb = br ? lb1 : lb0;
    for (int idx = tid; idx < 49*32; idx += 256) {
        int w = idx >> 5, s = idx & 31;
        int wy = w / 7, wx = w - wy * 7, ch = h*S_ + s;
        float acc = vsh[w][s] + lb[ch];
        #pragma unroll
        for (int dy = 0; dy < 3; dy++) {
            int yy = wy + dy - 1;
            if (yy < 0 || yy >= 7) continue;
            #pragma unroll
            for (int dx = 0; dx < 3; dx++) {
                int xx = wx + dx - 1;
                if (xx < 0 || xx >= 7) continue;
                acc += lw[ch*9 + dy*3 + dx] * vsh[yy*7+xx][s];
            }
        }
        g_v[(long)blk*1568 + w*32 + s] = acc;
    }
}

// ---------------- attention: fp16 q (FIXED load), packed f32x2 FMA ----------------
__global__ void __launch_bounds__(256)
attn_kernel(const __half* __restrict__ q, __half* __restrict__ a16) {
    int blk = blockIdx.x;
    int br = blk >> 7, bh = blk & 127, b = bh >> 3, h = bh & 7;
    int tid = threadIdx.x;
    __shared__ float ksh[49][32], vsh[49][32], osh[256][33];
    const float* kp = g_k + (long)blk * 1568;
    const float* vp = g_v + (long)blk * 1568;
    for (int idx = tid; idx < 1568; idx += 256) { ((float*)ksh)[idx] = kp[idx]; ((float*)vsh)[idx] = vp[idx]; }
    __syncthreads();

    int n0 = blockIdx.y * 256, n = n0 + tid;
    if (n < N_) {
        const __half* qp = q + ((long)b*N_ + n)*DIM + h*64 + br*32;
        uint64_t q2[16];
        // FIX: 32 halves = 4 x uint4 (16B each = 8 halves = 4 half2)
        #pragma unroll
        for (int v = 0; v < 4; v++) {
            uint4 t = *(const uint4*)(qp + v*8);
            const __half2* hp = (const __half2*)&t;
            #pragma unroll
            for (int k2 = 0; k2 < 4; k2++) {
                float2 f = __half22float2(hp[k2]);
                PACK2(q2[v*4 + k2], f.x, f.y);
            }
        }
        float p[49], m = -1e30f;
        #pragma unroll
        for (int j = 0; j < 49; j++) {
            uint64_t acc2 = 0;
            #pragma unroll
            for (int d = 0; d < 8; d++) {
                ulonglong2 kk = *(const ulonglong2*)&ksh[j][d*4];
                FMA2(acc2, q2[d*2], kk.x);
                FMA2(acc2, q2[d*2+1], kk.y);
            }
            float lo, hi; UNPACK2(lo, hi, acc2);
            p[j] = lo + hi; m = fmaxf(m, p[j]);
        }
        float sum = 0.f;
        #pragma unroll
        for (int j = 0; j < 49; j++) { p[j] = __expf(p[j] - m); sum += p[j]; }
        float inv = 1.f / sum;
        uint64_t o2[16];
        #pragma unroll
        for (int d = 0; d < 16; d++) o2[d] = 0;
        #pragma unroll
        for (int j = 0; j < 49; j++) {
            uint64_t pj2; PACK2(pj2, p[j], p[j]);
            #pragma unroll
            for (int d = 0; d < 8; d++) {
                ulonglong2 vv = *(const ulonglong2*)&vsh[j][d*4];
                FMA2(o2[d*2], pj2, vv.x);
                FMA2(o2[d*2+1], pj2, vv.y);
            }
        }
        #pragma unroll
        for (int d = 0; d < 16; d++) {
            float lo, hi; UNPACK2(lo, hi, o2[d]);
            osh[tid][d*2]   = lo * inv;
            osh[tid][d*2+1] = hi * inv;
        }
    }
    __syncthreads();
    int off = br * SD + h * S_;
    for (int idx = tid; idx < 256*16; idx += 256) {
        int qq = idx >> 4, dp = (idx & 15) * 2;
        int nn = n0 + qq;
        if (nn < N_) {
            long o = ((long)b*N_ + nn)*DIM + off + dp;
            *(__half2*)(a16 + o) = __floats2half2_rn(osh[qq][dp], osh[qq][dp+1]);
        }
    }
}

// ---------------- launch ----------------
extern "C" void kernel_launch(void* const* d_in, const int* in_sizes, int n_in,
                              void* d_out, int out_size) {
    const float* x       = (const float*)d_in[0];
    const float* q_w     = (const float*)d_in[3];
    const float* kv_dw_w = (const float*)d_in[4];
    const float* kv_dw_b = (const float*)d_in[5];
    const float* kv_pw_w = (const float*)d_in[6];
    const float* kv_pw_b = (const float*)d_in[7];
    const float* fc_w0   = (const float*)d_in[8];
    const float* fc_w1   = (const float*)d_in[9];
    const float* sg_w0   = (const float*)d_in[10];
    const float* sg_w1   = (const float*)d_in[11];
    const float* lw0     = (const float*)d_in[12];
    const float* lb0     = (const float*)d_in[13];
    const float* lw1     = (const float*)d_in[14];
    const float* lb1     = (const float*)d_in[15];
    const float* proj_w  = (const float*)d_in[16];
    const float* proj_b  = (const float*)d_in[17];
    float* out = (float*)d_out;

    __half *x16, *d116, *a316, *q16, *w16;
    cudaGetSymbolAddress((void**)&x16, g_x16);
    cudaGetSymbolAddress((void**)&d116, g_d116);
    cudaGetSymbolAddress((void**)&a316, g_a316);
    cudaGetSymbolAddress((void**)&q16, g_q16);
    cudaGetSymbolAddress((void**)&w16, g_w16);

    cudaFuncSetAttribute(gemm_dual, cudaFuncAttributeMaxDynamicSharedMemorySize, GSMEM);

    wsplit3_kernel<<<dim3(DIM*DIM/4/256, 3), 256>>>(q_w, kv_pw_w, proj_w, w16);
    dwconv_kernel<<<BN/8, 128>>>(x, kv_dw_w, kv_dw_b, d116, x16);

    GemmArgs kvA { d116, w16 + DIM*DIM,   kv_pw_b, nullptr, nullptr, 2 };
    GemmArgs qA  { x16,  w16,             nullptr, nullptr, q16,     1 };
    GemmArgs pA  { a316, w16 + 2*DIM*DIM, proj_b,  out,     nullptr, 0 };

    gemm_dual<<<dim3(BN/128, DIM/128, 2), 256, GSMEM>>>(kvA, qA);
    prep_kernel<<<256, 256>>>(fc_w0, fc_w1, sg_w0, sg_w1, lw0, lb0, lw1, lb1);
    attn_kernel<<<dim3(256, (N_+255)/256), 256>>>(q16, a316);
    gemm_dual<<<dim3(BN/128, DIM/128, 1), 256, GSMEM>>>(pA, pA);
}